// round 1
// baseline (speedup 1.0000x reference)
#include <cuda_runtime.h>
#include <cstdint>

#define NPIL   96000
#define MPTS   32
#define BATCH  8
#define NXc    432
#define NYc    496
#define NYNX   (NYc*NXc)          /* 214272 */
#define NCH    64
#define OUT_ELEMS (BATCH*NCH*NYNX) /* 109707264 */

// ---------------- device scratch (static, no allocation) ----------------
__device__ double d_stats[65];
__device__ float4 d_wbuf4[NPIL * 2];          // per pillar: (mx,my,mz,0),(cx,cy,cz,0)
__device__ int    d_winner[BATCH * NYNX];     // 6.9 MB
__device__ float4 d_U[NCH];                   // s * (A,B,C,D)
__device__ float4 d_G0[NCH];                  // s * g[0..3]
__device__ float4 d_G1[NCH];                  // s*g4, s*g5, t, 0

// ---------------- init: zero output, winner=-1, stats=0 ----------------
__global__ void init_kernel(float4* __restrict__ out4) {
    long long tid = (long long)blockIdx.x * blockDim.x + threadIdx.x;
    long long stride = (long long)gridDim.x * blockDim.x;
    const long long n4 = OUT_ELEMS / 4;
    float4 z = make_float4(0.f, 0.f, 0.f, 0.f);
    for (long long i = tid; i < n4; i += stride) out4[i] = z;
    const long long nw = (long long)BATCH * NYNX;
    for (long long i = tid; i < nw; i += stride) d_winner[i] = -1;
    if (blockIdx.x == 0 && threadIdx.x < 65) d_stats[threadIdx.x] = 0.0;
}

// ---------------- stats: 65 global moments + per-pillar w-vector ----------------
__global__ void stats_kernel(const float4* __restrict__ pil4,
                             const int4*  __restrict__ coords4,
                             const int*   __restrict__ nump) {
    int p = blockIdx.x * blockDim.x + threadIdx.x;
    float acc[65];
#pragma unroll
    for (int i = 0; i < 65; i++) acc[i] = 0.f;

    if (p < NPIL) {
        float sx=0.f, sy=0.f, sz=0.f, sw=0.f;
        float xx=0.f,xy=0.f,xz=0.f,xw=0.f,yy=0.f,yz=0.f,yw=0.f,zz=0.f,zw=0.f,ww=0.f;
        const float4* vp = pil4 + (size_t)p * MPTS;
#pragma unroll 8
        for (int m = 0; m < MPTS; m++) {
            float4 v = vp[m];
            sx += v.x; sy += v.y; sz += v.z; sw += v.w;
            xx = fmaf(v.x, v.x, xx); xy = fmaf(v.x, v.y, xy);
            xz = fmaf(v.x, v.z, xz); xw = fmaf(v.x, v.w, xw);
            yy = fmaf(v.y, v.y, yy); yz = fmaf(v.y, v.z, yz);
            yw = fmaf(v.y, v.w, yw);
            zz = fmaf(v.z, v.z, zz); zw = fmaf(v.z, v.w, zw);
            ww = fmaf(v.w, v.w, ww);
        }
        int4 cd = coords4[p];                // (b, z, y, x)
        float n = (float)nump[p];
        float mx = sx / n, my = sy / n, mz = sz / n;
        float ctrx = (float)cd.w * 0.16f + 0.08f;
        float ctry = (float)cd.z * 0.16f + (-39.6f);
        float ctrz = (float)cd.y * 4.0f  + (-1.0f);

        float sv[4] = {sx, sy, sz, sw};
        float w6[6] = {mx, my, mz, ctrx, ctry, ctrz};

        acc[0]=sx; acc[1]=sy; acc[2]=sz; acc[3]=sw;
        acc[4]=xx; acc[5]=xy; acc[6]=xz; acc[7]=xw; acc[8]=yy;
        acc[9]=yz; acc[10]=yw; acc[11]=zz; acc[12]=zw; acc[13]=ww;
#pragma unroll
        for (int j = 0; j < 6; j++) acc[14 + j] = w6[j];
#pragma unroll
        for (int i = 0; i < 4; i++)
#pragma unroll
            for (int j = 0; j < 6; j++) acc[20 + i*6 + j] = sv[i] * w6[j];
        {
            int k = 0;
#pragma unroll
            for (int i = 0; i < 6; i++)
#pragma unroll
                for (int j = i; j < 6; j++) { acc[44 + k] = w6[i] * w6[j]; k++; }
        }
        d_wbuf4[p*2 + 0] = make_float4(mx, my, mz, 0.f);
        d_wbuf4[p*2 + 1] = make_float4(ctrx, ctry, ctrz, 0.f);
    }

    // warp tree-reduce all 65 partials, lane0 -> double atomics
#pragma unroll
    for (int i = 0; i < 65; i++) {
        float v = acc[i];
        v += __shfl_xor_sync(0xffffffffu, v, 16);
        v += __shfl_xor_sync(0xffffffffu, v, 8);
        v += __shfl_xor_sync(0xffffffffu, v, 4);
        v += __shfl_xor_sync(0xffffffffu, v, 2);
        v += __shfl_xor_sync(0xffffffffu, v, 1);
        acc[i] = v;
    }
    if ((threadIdx.x & 31) == 0) {
#pragma unroll
        for (int i = 0; i < 65; i++) atomicAdd(&d_stats[i], (double)acc[i]);
    }
}

// ---------------- finalize: closed-form BN params per channel ----------------
__global__ void finalize_kernel(const float* __restrict__ W,
                                const float* __restrict__ gamma,
                                const float* __restrict__ beta) {
    int c = threadIdx.x;
    if (c >= NCH) return;

    double A = (double)W[0*NCH+c] + (double)W[4*NCH+c] + (double)W[7*NCH+c];
    double Bv= (double)W[1*NCH+c] + (double)W[5*NCH+c] + (double)W[8*NCH+c];
    double Cv= (double)W[2*NCH+c] + (double)W[6*NCH+c] + (double)W[9*NCH+c];
    double Dv= (double)W[3*NCH+c];
    double u[4] = {A, Bv, Cv, Dv};
    double g[6];
#pragma unroll
    for (int j = 0; j < 6; j++) g[j] = (double)W[(4 + j)*NCH + c];

    double st[65];
#pragma unroll
    for (int i = 0; i < 65; i++) st[i] = d_stats[i];

    double S1 = u[0]*st[0] + u[1]*st[1] + u[2]*st[2] + u[3]*st[3];
    double sg = 0.0;
#pragma unroll
    for (int j = 0; j < 6; j++) sg += g[j] * st[14 + j];
    S1 -= (double)MPTS * sg;

    double Q1 = st[4]*A*A + st[8]*Bv*Bv + st[11]*Cv*Cv + st[13]*Dv*Dv
              + 2.0*(st[5]*A*Bv + st[6]*A*Cv + st[7]*A*Dv
                   + st[9]*Bv*Cv + st[10]*Bv*Dv + st[12]*Cv*Dv);
    double Q2 = 0.0;
#pragma unroll
    for (int i = 0; i < 4; i++)
#pragma unroll
        for (int j = 0; j < 6; j++) Q2 += u[i] * st[20 + i*6 + j] * g[j];
    double Q3 = 0.0;
    {
        int k = 0;
#pragma unroll
        for (int i = 0; i < 6; i++)
#pragma unroll
            for (int j = i; j < 6; j++) {
                Q3 += (i == j ? 1.0 : 2.0) * g[i] * g[j] * st[44 + k];
                k++;
            }
    }
    double S2 = Q1 - 2.0*Q2 + (double)MPTS * Q3;

    double N   = (double)NPIL * (double)MPTS;
    double mu  = S1 / N;
    double var = S2 / N - mu * mu;
    double s   = (double)gamma[c] / sqrt(var + 1e-3);
    double t   = (double)beta[c] - s * mu;

    d_U[c]  = make_float4((float)(s*A), (float)(s*Bv), (float)(s*Cv), (float)(s*Dv));
    d_G0[c] = make_float4((float)(s*g[0]), (float)(s*g[1]), (float)(s*g[2]), (float)(s*g[3]));
    d_G1[c] = make_float4((float)(s*g[4]), (float)(s*g[5]), (float)t, 0.f);
}

// ---------------- winner: emulate JAX scatter "last update wins" ----------------
__global__ void winner_kernel(const int4* __restrict__ coords4) {
    int p = blockIdx.x * blockDim.x + threadIdx.x;
    if (p >= NPIL) return;
    int4 cd = coords4[p];
    int cell = cd.y + cd.z * NXc + cd.w;
    atomicMax(&d_winner[cd.x * NYNX + cell], p);
}

// ---------------- main: fused GEMM + BN + relu + maxpool + scatter ----------------
__global__ void __launch_bounds__(256) main_kernel(const float4* __restrict__ pil4,
                                                   const int4*  __restrict__ coords4,
                                                   float* __restrict__ out) {
    __shared__ float4 sv[4][MPTS];
    int tid = threadIdx.x;
    int pi  = tid >> 6;          // 0..3 pillar within block
    int c   = tid & 63;          // channel
    int pbase = blockIdx.x * 4;

    if (tid < 128) {
        sv[tid >> 5][tid & 31] = pil4[(size_t)(pbase + (tid >> 5)) * MPTS + (tid & 31)];
    }
    __syncthreads();

    int p = pbase + pi;
    float4 U = d_U[c];
    float4 a = d_G0[c];
    float4 b = d_G1[c];
    float4 w0 = d_wbuf4[p*2 + 0];
    float4 w1 = d_wbuf4[p*2 + 1];
    float cst = b.z - (w0.x*a.x + w0.y*a.y + w0.z*a.z
                     + w1.x*a.w + w1.y*b.x + w1.z*b.y);

    float q = -3.4e38f;
#pragma unroll 8
    for (int m = 0; m < MPTS; m++) {
        float4 v = sv[pi][m];
        float d = fmaf(v.x, U.x, fmaf(v.y, U.y, fmaf(v.z, U.z, v.w * U.w)));
        q = fmaxf(q, d);
    }
    float val = fmaxf(q + cst, 0.0f);

    int4 cd = coords4[p];
    int cell = cd.y + cd.z * NXc + cd.w;
    int cb   = cd.x * NYNX + cell;
    if (d_winner[cb] == p)
        out[(size_t)(cd.x * NCH + c) * NYNX + cell] = val;
}

// ---------------- launch ----------------
extern "C" void kernel_launch(void* const* d_in, const int* in_sizes, int n_in,
                              void* d_out, int out_size) {
    const float4* pil4    = (const float4*)d_in[0];
    const int4*   coords4 = (const int4*)d_in[1];
    const int*    nump    = (const int*)d_in[2];
    const float*  W       = (const float*)d_in[3];
    const float*  gamma   = (const float*)d_in[4];
    const float*  beta    = (const float*)d_in[5];
    float* out = (float*)d_out;

    init_kernel<<<4096, 256>>>((float4*)d_out);
    stats_kernel<<<(NPIL + 255) / 256, 256>>>(pil4, coords4, nump);
    finalize_kernel<<<1, 64>>>(W, gamma, beta);
    winner_kernel<<<(NPIL + 255) / 256, 256>>>(coords4);
    main_kernel<<<NPIL / 4, 256>>>(pil4, coords4, out);
}

// round 2
// speedup vs baseline: 1.3178x; 1.3178x over previous
#include <cuda_runtime.h>
#include <cstdint>

#define NPIL   96000
#define MPTS   32
#define BATCH  8
#define NXc    432
#define NYc    496
#define NYNX   (NYc*NXc)          /* 214272 */
#define NCH    64
#define OUT_ELEMS (BATCH*NCH*NYNX) /* 109707264 */

// ---------------- device scratch (static, no allocation) ----------------
__device__ double d_stats[65];
__device__ float4 d_wbuf4[NPIL * 2];          // per pillar: (mx,my,mz,0),(cx,cy,cz,0)
__device__ int    d_winner[BATCH * NYNX];     // 6.9 MB
__device__ float4 d_U[NCH];                   // s * (A,B,C,D)
__device__ float4 d_G0[NCH];                  // s * g[0..3]
__device__ float4 d_G1[NCH];                  // s*g4, s*g5, t, 0

// ---------------- init: zero output, winner=-1, stats=0 ----------------
__global__ void init_kernel(float4* __restrict__ out4) {
    long long tid = (long long)blockIdx.x * blockDim.x + threadIdx.x;
    long long stride = (long long)gridDim.x * blockDim.x;
    const long long n4 = OUT_ELEMS / 4;
    float4 z = make_float4(0.f, 0.f, 0.f, 0.f);
    for (long long i = tid; i < n4; i += stride) out4[i] = z;
    const long long nw = (long long)BATCH * NYNX;
    for (long long i = tid; i < nw; i += stride) d_winner[i] = -1;
    if (blockIdx.x == 0 && threadIdx.x < 65) d_stats[threadIdx.x] = 0.0;
}

// ---------------- stats + winner: one pass over pillar data ----------------
__global__ void __launch_bounds__(256) stats_kernel(const float4* __restrict__ pil4,
                             const int4*  __restrict__ coords4,
                             const int*   __restrict__ nump) {
    __shared__ float sred[8][65];
    int p = blockIdx.x * blockDim.x + threadIdx.x;
    int lane = threadIdx.x & 31;
    int warp = threadIdx.x >> 5;

    float acc[65];
#pragma unroll
    for (int i = 0; i < 65; i++) acc[i] = 0.f;

    if (p < NPIL) {
        float sx=0.f, sy=0.f, sz=0.f, sw=0.f;
        float xx=0.f,xy=0.f,xz=0.f,xw=0.f,yy=0.f,yz=0.f,yw=0.f,zz=0.f,zw=0.f,ww=0.f;
        const float4* vp = pil4 + (size_t)p * MPTS;
#pragma unroll 8
        for (int m = 0; m < MPTS; m++) {
            float4 v = vp[m];
            sx += v.x; sy += v.y; sz += v.z; sw += v.w;
            xx = fmaf(v.x, v.x, xx); xy = fmaf(v.x, v.y, xy);
            xz = fmaf(v.x, v.z, xz); xw = fmaf(v.x, v.w, xw);
            yy = fmaf(v.y, v.y, yy); yz = fmaf(v.y, v.z, yz);
            yw = fmaf(v.y, v.w, yw);
            zz = fmaf(v.z, v.z, zz); zw = fmaf(v.z, v.w, zw);
            ww = fmaf(v.w, v.w, ww);
        }
        int4 cd = coords4[p];                // (b, z, y, x)

        // winner scatter-order emulation (last index wins)
        int cell = cd.y + cd.z * NXc + cd.w;
        atomicMax(&d_winner[cd.x * NYNX + cell], p);

        float n = (float)nump[p];
        float mx = sx / n, my = sy / n, mz = sz / n;
        float ctrx = (float)cd.w * 0.16f + 0.08f;
        float ctry = (float)cd.z * 0.16f + (-39.6f);
        float ctrz = (float)cd.y * 4.0f  + (-1.0f);

        float sv[4] = {sx, sy, sz, sw};
        float w6[6] = {mx, my, mz, ctrx, ctry, ctrz};

        acc[0]=sx; acc[1]=sy; acc[2]=sz; acc[3]=sw;
        acc[4]=xx; acc[5]=xy; acc[6]=xz; acc[7]=xw; acc[8]=yy;
        acc[9]=yz; acc[10]=yw; acc[11]=zz; acc[12]=zw; acc[13]=ww;
#pragma unroll
        for (int j = 0; j < 6; j++) acc[14 + j] = w6[j];
#pragma unroll
        for (int i = 0; i < 4; i++)
#pragma unroll
            for (int j = 0; j < 6; j++) acc[20 + i*6 + j] = sv[i] * w6[j];
        {
            int k = 0;
#pragma unroll
            for (int i = 0; i < 6; i++)
#pragma unroll
                for (int j = i; j < 6; j++) { acc[44 + k] = w6[i] * w6[j]; k++; }
        }
        d_wbuf4[p*2 + 0] = make_float4(mx, my, mz, 0.f);
        d_wbuf4[p*2 + 1] = make_float4(ctrx, ctry, ctrz, 0.f);
    }

    // warp tree-reduce all 65 partials
#pragma unroll
    for (int i = 0; i < 65; i++) {
        float v = acc[i];
        v += __shfl_xor_sync(0xffffffffu, v, 16);
        v += __shfl_xor_sync(0xffffffffu, v, 8);
        v += __shfl_xor_sync(0xffffffffu, v, 4);
        v += __shfl_xor_sync(0xffffffffu, v, 2);
        v += __shfl_xor_sync(0xffffffffu, v, 1);
        acc[i] = v;
    }
    if (lane == 0) {
#pragma unroll
        for (int i = 0; i < 65; i++) sred[warp][i] = acc[i];
    }
    __syncthreads();

    // one double atomic per stat per block (375 per address total)
    if (threadIdx.x < 65) {
        float s = 0.f;
#pragma unroll
        for (int w = 0; w < 8; w++) s += sred[w][threadIdx.x];
        atomicAdd(&d_stats[threadIdx.x], (double)s);
    }
}

// ---------------- finalize: closed-form BN params per channel ----------------
__global__ void finalize_kernel(const float* __restrict__ W,
                                const float* __restrict__ gamma,
                                const float* __restrict__ beta) {
    int c = threadIdx.x;
    if (c >= NCH) return;

    double A = (double)W[0*NCH+c] + (double)W[4*NCH+c] + (double)W[7*NCH+c];
    double Bv= (double)W[1*NCH+c] + (double)W[5*NCH+c] + (double)W[8*NCH+c];
    double Cv= (double)W[2*NCH+c] + (double)W[6*NCH+c] + (double)W[9*NCH+c];
    double Dv= (double)W[3*NCH+c];
    double u[4] = {A, Bv, Cv, Dv};
    double g[6];
#pragma unroll
    for (int j = 0; j < 6; j++) g[j] = (double)W[(4 + j)*NCH + c];

    double st[65];
#pragma unroll
    for (int i = 0; i < 65; i++) st[i] = d_stats[i];

    double S1 = u[0]*st[0] + u[1]*st[1] + u[2]*st[2] + u[3]*st[3];
    double sg = 0.0;
#pragma unroll
    for (int j = 0; j < 6; j++) sg += g[j] * st[14 + j];
    S1 -= (double)MPTS * sg;

    double Q1 = st[4]*A*A + st[8]*Bv*Bv + st[11]*Cv*Cv + st[13]*Dv*Dv
              + 2.0*(st[5]*A*Bv + st[6]*A*Cv + st[7]*A*Dv
                   + st[9]*Bv*Cv + st[10]*Bv*Dv + st[12]*Cv*Dv);
    double Q2 = 0.0;
#pragma unroll
    for (int i = 0; i < 4; i++)
#pragma unroll
        for (int j = 0; j < 6; j++) Q2 += u[i] * st[20 + i*6 + j] * g[j];
    double Q3 = 0.0;
    {
        int k = 0;
#pragma unroll
        for (int i = 0; i < 6; i++)
#pragma unroll
            for (int j = i; j < 6; j++) {
                Q3 += (i == j ? 1.0 : 2.0) * g[i] * g[j] * st[44 + k];
                k++;
            }
    }
    double S2 = Q1 - 2.0*Q2 + (double)MPTS * Q3;

    double N   = (double)NPIL * (double)MPTS;
    double mu  = S1 / N;
    double var = S2 / N - mu * mu;
    double s   = (double)gamma[c] / sqrt(var + 1e-3);
    double t   = (double)beta[c] - s * mu;

    d_U[c]  = make_float4((float)(s*A), (float)(s*Bv), (float)(s*Cv), (float)(s*Dv));
    d_G0[c] = make_float4((float)(s*g[0]), (float)(s*g[1]), (float)(s*g[2]), (float)(s*g[3]));
    d_G1[c] = make_float4((float)(s*g[4]), (float)(s*g[5]), (float)t, 0.f);
}

// ---------------- main: fused GEMM + BN + relu + maxpool + scatter ----------------
__global__ void __launch_bounds__(256) main_kernel(const float4* __restrict__ pil4,
                                                   const int4*  __restrict__ coords4,
                                                   float* __restrict__ out) {
    __shared__ float4 sv[4][MPTS];
    int tid = threadIdx.x;
    int pi  = tid >> 6;          // 0..3 pillar within block
    int c   = tid & 63;          // channel
    int pbase = blockIdx.x * 4;

    if (tid < 128) {
        sv[tid >> 5][tid & 31] = pil4[(size_t)(pbase + (tid >> 5)) * MPTS + (tid & 31)];
    }
    __syncthreads();

    int p = pbase + pi;
    int4 cd = coords4[p];
    int cell = cd.y + cd.z * NXc + cd.w;
    int cb   = cd.x * NYNX + cell;
    if (d_winner[cb] != p) return;

    float4 U = d_U[c];
    float4 a = d_G0[c];
    float4 b = d_G1[c];
    float4 w0 = d_wbuf4[p*2 + 0];
    float4 w1 = d_wbuf4[p*2 + 1];
    float cst = b.z - (w0.x*a.x + w0.y*a.y + w0.z*a.z
                     + w1.x*a.w + w1.y*b.x + w1.z*b.y);

    float q = -3.4e38f;
#pragma unroll 8
    for (int m = 0; m < MPTS; m++) {
        float4 v = sv[pi][m];
        float d = fmaf(v.x, U.x, fmaf(v.y, U.y, fmaf(v.z, U.z, v.w * U.w)));
        q = fmaxf(q, d);
    }
    float val = fmaxf(q + cst, 0.0f);

    out[(size_t)(cd.x * NCH + c) * NYNX + cell] = val;
}

// ---------------- launch ----------------
extern "C" void kernel_launch(void* const* d_in, const int* in_sizes, int n_in,
                              void* d_out, int out_size) {
    const float4* pil4    = (const float4*)d_in[0];
    const int4*   coords4 = (const int4*)d_in[1];
    const int*    nump    = (const int*)d_in[2];
    const float*  W       = (const float*)d_in[3];
    const float*  gamma   = (const float*)d_in[4];
    const float*  beta    = (const float*)d_in[5];
    float* out = (float*)d_out;

    init_kernel<<<4096, 256>>>((float4*)d_out);
    stats_kernel<<<(NPIL + 255) / 256, 256>>>(pil4, coords4, nump);
    finalize_kernel<<<1, 64>>>(W, gamma, beta);
    main_kernel<<<NPIL / 4, 256>>>(pil4, coords4, out);
}

// round 3
// speedup vs baseline: 1.9168x; 1.4545x over previous
#include <cuda_runtime.h>
#include <cstdint>

#define NPIL   96000
#define MPTS   32
#define BATCH  8
#define NXc    432
#define NYc    496
#define NYNX   (NYc*NXc)          /* 214272 */
#define NCH    64
#define OUT_ELEMS (BATCH*NCH*NYNX) /* 109707264 */

#define STATS_BLOCKS 375          /* ceil(96000/256) */
#define TOTAL_BLOCKS 4096

// ---------------- device scratch (static, no allocation) ----------------
__device__ double d_stats[65];
__device__ float4 d_wbuf4[NPIL * 2];          // per pillar: (mx,my,mz,0),(cx,cy,cz,0)
__device__ int    d_winner[BATCH * NYNX];     // 6.9 MB
__device__ float4 d_U[NCH];                   // s * (A,B,C,D)
__device__ float4 d_G0[NCH];                  // s * g[0..3]
__device__ float4 d_G1[NCH];                  // s*g4, s*g5, t, 0

// ---------------- pre-init: winner=-1, stats=0 (tiny) ----------------
__global__ void pre_init_kernel() {
    int i = blockIdx.x * blockDim.x + threadIdx.x;
    int stride = gridDim.x * blockDim.x;
    const int nw = BATCH * NYNX;
    for (int j = i; j < nw; j += stride) d_winner[j] = -1;
    if (i < 65) d_stats[i] = 0.0;
}

// ---------------- fused: stats+winner (blocks<375) | zero output (rest) ----------------
__global__ void __launch_bounds__(256) stats_zero_kernel(const float4* __restrict__ pil4,
                             const int4*  __restrict__ coords4,
                             const int*   __restrict__ nump,
                             float4* __restrict__ out4) {
    if (blockIdx.x >= STATS_BLOCKS) {
        // -------- zero-fill slice of output --------
        const long long n4 = OUT_ELEMS / 4;
        long long idx = (long long)(blockIdx.x - STATS_BLOCKS) * blockDim.x + threadIdx.x;
        long long stride = (long long)(TOTAL_BLOCKS - STATS_BLOCKS) * blockDim.x;
        float4 z = make_float4(0.f, 0.f, 0.f, 0.f);
        for (long long i = idx; i < n4; i += stride) out4[i] = z;
        return;
    }

    __shared__ float sred[8][65];
    int p = blockIdx.x * blockDim.x + threadIdx.x;
    int lane = threadIdx.x & 31;
    int warp = threadIdx.x >> 5;

    float acc[65];
#pragma unroll
    for (int i = 0; i < 65; i++) acc[i] = 0.f;

    if (p < NPIL) {
        float sx=0.f, sy=0.f, sz=0.f, sw=0.f;
        float xx=0.f,xy=0.f,xz=0.f,xw=0.f,yy=0.f,yz=0.f,yw=0.f,zz=0.f,zw=0.f,ww=0.f;
        const float4* vp = pil4 + (size_t)p * MPTS;
#pragma unroll 8
        for (int m = 0; m < MPTS; m++) {
            float4 v = vp[m];
            sx += v.x; sy += v.y; sz += v.z; sw += v.w;
            xx = fmaf(v.x, v.x, xx); xy = fmaf(v.x, v.y, xy);
            xz = fmaf(v.x, v.z, xz); xw = fmaf(v.x, v.w, xw);
            yy = fmaf(v.y, v.y, yy); yz = fmaf(v.y, v.z, yz);
            yw = fmaf(v.y, v.w, yw);
            zz = fmaf(v.z, v.z, zz); zw = fmaf(v.z, v.w, zw);
            ww = fmaf(v.w, v.w, ww);
        }
        int4 cd = coords4[p];                // (b, z, y, x)

        // winner scatter-order emulation (last index wins)
        int cell = cd.y + cd.z * NXc + cd.w;
        atomicMax(&d_winner[cd.x * NYNX + cell], p);

        float n = (float)nump[p];
        float mx = sx / n, my = sy / n, mz = sz / n;
        float ctrx = (float)cd.w * 0.16f + 0.08f;
        float ctry = (float)cd.z * 0.16f + (-39.6f);
        float ctrz = (float)cd.y * 4.0f  + (-1.0f);

        float sv[4] = {sx, sy, sz, sw};
        float w6[6] = {mx, my, mz, ctrx, ctry, ctrz};

        acc[0]=sx; acc[1]=sy; acc[2]=sz; acc[3]=sw;
        acc[4]=xx; acc[5]=xy; acc[6]=xz; acc[7]=xw; acc[8]=yy;
        acc[9]=yz; acc[10]=yw; acc[11]=zz; acc[12]=zw; acc[13]=ww;
#pragma unroll
        for (int j = 0; j < 6; j++) acc[14 + j] = w6[j];
#pragma unroll
        for (int i = 0; i < 4; i++)
#pragma unroll
            for (int j = 0; j < 6; j++) acc[20 + i*6 + j] = sv[i] * w6[j];
        {
            int k = 0;
#pragma unroll
            for (int i = 0; i < 6; i++)
#pragma unroll
                for (int j = i; j < 6; j++) { acc[44 + k] = w6[i] * w6[j]; k++; }
        }
        d_wbuf4[p*2 + 0] = make_float4(mx, my, mz, 0.f);
        d_wbuf4[p*2 + 1] = make_float4(ctrx, ctry, ctrz, 0.f);
    }

    // warp tree-reduce all 65 partials
#pragma unroll
    for (int i = 0; i < 65; i++) {
        float v = acc[i];
        v += __shfl_xor_sync(0xffffffffu, v, 16);
        v += __shfl_xor_sync(0xffffffffu, v, 8);
        v += __shfl_xor_sync(0xffffffffu, v, 4);
        v += __shfl_xor_sync(0xffffffffu, v, 2);
        v += __shfl_xor_sync(0xffffffffu, v, 1);
        acc[i] = v;
    }
    if (lane == 0) {
#pragma unroll
        for (int i = 0; i < 65; i++) sred[warp][i] = acc[i];
    }
    __syncthreads();

    if (threadIdx.x < 65) {
        float s = 0.f;
#pragma unroll
        for (int w = 0; w < 8; w++) s += sred[w][threadIdx.x];
        atomicAdd(&d_stats[threadIdx.x], (double)s);
    }
}

// ---------------- finalize: closed-form BN params per channel ----------------
__global__ void finalize_kernel(const float* __restrict__ W,
                                const float* __restrict__ gamma,
                                const float* __restrict__ beta) {
    int c = threadIdx.x;
    if (c >= NCH) return;

    double A = (double)W[0*NCH+c] + (double)W[4*NCH+c] + (double)W[7*NCH+c];
    double Bv= (double)W[1*NCH+c] + (double)W[5*NCH+c] + (double)W[8*NCH+c];
    double Cv= (double)W[2*NCH+c] + (double)W[6*NCH+c] + (double)W[9*NCH+c];
    double Dv= (double)W[3*NCH+c];
    double u[4] = {A, Bv, Cv, Dv};
    double g[6];
#pragma unroll
    for (int j = 0; j < 6; j++) g[j] = (double)W[(4 + j)*NCH + c];

    double st[65];
#pragma unroll
    for (int i = 0; i < 65; i++) st[i] = d_stats[i];

    double S1 = u[0]*st[0] + u[1]*st[1] + u[2]*st[2] + u[3]*st[3];
    double sg = 0.0;
#pragma unroll
    for (int j = 0; j < 6; j++) sg += g[j] * st[14 + j];
    S1 -= (double)MPTS * sg;

    double Q1 = st[4]*A*A + st[8]*Bv*Bv + st[11]*Cv*Cv + st[13]*Dv*Dv
              + 2.0*(st[5]*A*Bv + st[6]*A*Cv + st[7]*A*Dv
                   + st[9]*Bv*Cv + st[10]*Bv*Dv + st[12]*Cv*Dv);
    double Q2 = 0.0;
#pragma unroll
    for (int i = 0; i < 4; i++)
#pragma unroll
        for (int j = 0; j < 6; j++) Q2 += u[i] * st[20 + i*6 + j] * g[j];
    double Q3 = 0.0;
    {
        int k = 0;
#pragma unroll
        for (int i = 0; i < 6; i++)
#pragma unroll
            for (int j = i; j < 6; j++) {
                Q3 += (i == j ? 1.0 : 2.0) * g[i] * g[j] * st[44 + k];
                k++;
            }
    }
    double S2 = Q1 - 2.0*Q2 + (double)MPTS * Q3;

    double N   = (double)NPIL * (double)MPTS;
    double mu  = S1 / N;
    double var = S2 / N - mu * mu;
    double s   = (double)gamma[c] / sqrt(var + 1e-3);
    double t   = (double)beta[c] - s * mu;

    d_U[c]  = make_float4((float)(s*A), (float)(s*Bv), (float)(s*Cv), (float)(s*Dv));
    d_G0[c] = make_float4((float)(s*g[0]), (float)(s*g[1]), (float)(s*g[2]), (float)(s*g[3]));
    d_G1[c] = make_float4((float)(s*g[4]), (float)(s*g[5]), (float)t, 0.f);
}

// ---------------- main: packed-f32x2 GEMM + BN + relu + maxpool + scatter ----------------
__global__ void __launch_bounds__(256) main_kernel(const float4* __restrict__ pil4,
                                                   const int4*  __restrict__ coords4,
                                                   float* __restrict__ out) {
    // packed point-pair layout per pillar: 16 pairs x 32B:
    //   pair j: [x2j x2j+1 y2j y2j+1 | z2j z2j+1 w2j w2j+1]
    __shared__ float spack[4][128];

    int tid = threadIdx.x;
    int pi  = tid >> 6;          // pillar slot 0..3
    int c   = tid & 63;          // channel
    int pbase = blockIdx.x * 4;
    int p = pbase + pi;

    // issue the dependent coord->winner chain as early as possible
    int4 cd = coords4[p];
    int cell = cd.y + cd.z * NXc + cd.w;
    int cb   = cd.x * NYNX + cell;
    int win  = d_winner[cb];

    // pack 4 pillars into smem (128 threads, one point each)
    if (tid < 128) {
        int lp = tid >> 5;       // pillar slot
        int m  = tid & 31;       // point
        float4 v = pil4[(size_t)(pbase + lp) * MPTS + m];
        float* sp = &spack[lp][(m >> 1) * 8 + (m & 1)];
        sp[0] = v.x; sp[2] = v.y; sp[4] = v.z; sp[6] = v.w;
    }

    // per-channel params (L1-resident after first blocks)
    float4 U = d_U[c];
    float4 a = d_G0[c];
    float4 b = d_G1[c];
    float4 w0 = d_wbuf4[p*2 + 0];
    float4 w1 = d_wbuf4[p*2 + 1];

    __syncthreads();
    if (win != p) return;

    float cst = b.z - (w0.x*a.x + w0.y*a.y + w0.z*a.z
                     + w1.x*a.w + w1.y*b.x + w1.z*b.y);

    // splat channel weights into packed f32x2
    unsigned long long Ux2, Uy2, Uz2, Uw2;
    asm("mov.b64 %0, {%1,%1};" : "=l"(Ux2) : "f"(U.x));
    asm("mov.b64 %0, {%1,%1};" : "=l"(Uy2) : "f"(U.y));
    asm("mov.b64 %0, {%1,%1};" : "=l"(Uz2) : "f"(U.z));
    asm("mov.b64 %0, {%1,%1};" : "=l"(Uw2) : "f"(U.w));

    const ulonglong2* sp2 = (const ulonglong2*)&spack[pi][0];

    float q0 = -3.4e38f, q1 = -3.4e38f;
#pragma unroll
    for (int j = 0; j < 16; j++) {
        ulonglong2 P0 = sp2[j*2 + 0];    // {vx2, vy2}
        ulonglong2 P1 = sp2[j*2 + 1];    // {vz2, vw2}
        unsigned long long d;
        asm("mul.rn.f32x2 %0, %1, %2;"     : "=l"(d) : "l"(P1.y), "l"(Uw2));
        asm("fma.rn.f32x2 %0, %1, %2, %0;" : "+l"(d) : "l"(P1.x), "l"(Uz2));
        asm("fma.rn.f32x2 %0, %1, %2, %0;" : "+l"(d) : "l"(P0.y), "l"(Uy2));
        asm("fma.rn.f32x2 %0, %1, %2, %0;" : "+l"(d) : "l"(P0.x), "l"(Ux2));
        float lo, hi;
        asm("mov.b64 {%0,%1}, %2;" : "=f"(lo), "=f"(hi) : "l"(d));
        q0 = fmaxf(q0, lo);
        q1 = fmaxf(q1, hi);
    }
    float val = fmaxf(fmaxf(q0, q1) + cst, 0.0f);

    if (val > 0.0f)   // output already zero-initialized
        out[(size_t)(cd.x * NCH + c) * NYNX + cell] = val;
}

// ---------------- launch ----------------
extern "C" void kernel_launch(void* const* d_in, const int* in_sizes, int n_in,
                              void* d_out, int out_size) {
    const float4* pil4    = (const float4*)d_in[0];
    const int4*   coords4 = (const int4*)d_in[1];
    const int*    nump    = (const int*)d_in[2];
    const float*  W       = (const float*)d_in[3];
    const float*  gamma   = (const float*)d_in[4];
    const float*  beta    = (const float*)d_in[5];
    float* out = (float*)d_out;

    pre_init_kernel<<<1024, 256>>>();
    stats_zero_kernel<<<TOTAL_BLOCKS, 256>>>(pil4, coords4, nump, (float4*)d_out);
    finalize_kernel<<<1, 64>>>(W, gamma, beta);
    main_kernel<<<NPIL / 4, 256>>>(pil4, coords4, out);
}

// round 4
// speedup vs baseline: 2.0668x; 1.0783x over previous
#include <cuda_runtime.h>
#include <cstdint>

#define NPIL   96000
#define MPTS   32
#define BATCH  8
#define NXc    432
#define NYc    496
#define NYNX   (NYc*NXc)          /* 214272 */
#define NCH    64
#define CHUNK  128
#define NCHUNK (NYNX / CHUNK)     /* 1674 exactly */
#define MAXW   32
#define VPITCH 33                 /* vals row pitch (conflict-free) */

// ---------------- device scratch (static, no allocation) ----------------
__device__ double d_stats[65];
__device__ float4 d_wbuf4[NPIL * 2];          // per pillar: (mx,my,mz,0),(cx,cy,cz,0)
__device__ int    d_winner[BATCH * NYNX];     // 6.9 MB
__device__ float4 d_U[NCH];                   // s * (A,B,C,D)
__device__ float4 d_G0[NCH];                  // s * g[0..3]
__device__ float4 d_G1[NCH];                  // s*g4, s*g5, t, 0

// ---------------- pre-init: winner=-1, stats=0 ----------------
__global__ void pre_init_kernel() {
    int i = blockIdx.x * blockDim.x + threadIdx.x;
    int stride = gridDim.x * blockDim.x;
    const int nw = BATCH * NYNX;
    int4* w4 = (int4*)d_winner;
    int4 m1 = make_int4(-1, -1, -1, -1);
    for (int j = i; j < nw / 4; j += stride) w4[j] = m1;
    if (i < 65) d_stats[i] = 0.0;
}

// ---------------- stats + winner + wbuf: one pass over pillar data ----------------
__global__ void __launch_bounds__(256) stats_kernel(const float4* __restrict__ pil4,
                             const int4*  __restrict__ coords4,
                             const int*   __restrict__ nump) {
    __shared__ float sred[8][65];
    int p = blockIdx.x * blockDim.x + threadIdx.x;
    int lane = threadIdx.x & 31;
    int warp = threadIdx.x >> 5;

    float acc[65];
#pragma unroll
    for (int i = 0; i < 65; i++) acc[i] = 0.f;

    if (p < NPIL) {
        float sx=0.f, sy=0.f, sz=0.f, sw=0.f;
        float xx=0.f,xy=0.f,xz=0.f,xw=0.f,yy=0.f,yz=0.f,yw=0.f,zz=0.f,zw=0.f,ww=0.f;
        const float4* vp = pil4 + (size_t)p * MPTS;
#pragma unroll 8
        for (int m = 0; m < MPTS; m++) {
            float4 v = vp[m];
            sx += v.x; sy += v.y; sz += v.z; sw += v.w;
            xx = fmaf(v.x, v.x, xx); xy = fmaf(v.x, v.y, xy);
            xz = fmaf(v.x, v.z, xz); xw = fmaf(v.x, v.w, xw);
            yy = fmaf(v.y, v.y, yy); yz = fmaf(v.y, v.z, yz);
            yw = fmaf(v.y, v.w, yw);
            zz = fmaf(v.z, v.z, zz); zw = fmaf(v.z, v.w, zw);
            ww = fmaf(v.w, v.w, ww);
        }
        int4 cd = coords4[p];                // (b, z, y, x)

        // winner scatter-order emulation (last index wins)
        int cell = cd.y + cd.z * NXc + cd.w;
        atomicMax(&d_winner[cd.x * NYNX + cell], p);

        float n = (float)nump[p];
        float mx = sx / n, my = sy / n, mz = sz / n;
        float ctrx = (float)cd.w * 0.16f + 0.08f;
        float ctry = (float)cd.z * 0.16f + (-39.6f);
        float ctrz = (float)cd.y * 4.0f  + (-1.0f);

        float sv[4] = {sx, sy, sz, sw};
        float w6[6] = {mx, my, mz, ctrx, ctry, ctrz};

        acc[0]=sx; acc[1]=sy; acc[2]=sz; acc[3]=sw;
        acc[4]=xx; acc[5]=xy; acc[6]=xz; acc[7]=xw; acc[8]=yy;
        acc[9]=yz; acc[10]=yw; acc[11]=zz; acc[12]=zw; acc[13]=ww;
#pragma unroll
        for (int j = 0; j < 6; j++) acc[14 + j] = w6[j];
#pragma unroll
        for (int i = 0; i < 4; i++)
#pragma unroll
            for (int j = 0; j < 6; j++) acc[20 + i*6 + j] = sv[i] * w6[j];
        {
            int k = 0;
#pragma unroll
            for (int i = 0; i < 6; i++)
#pragma unroll
                for (int j = i; j < 6; j++) { acc[44 + k] = w6[i] * w6[j]; k++; }
        }
        d_wbuf4[p*2 + 0] = make_float4(mx, my, mz, 0.f);
        d_wbuf4[p*2 + 1] = make_float4(ctrx, ctry, ctrz, 0.f);
    }

    // warp tree-reduce all 65 partials
#pragma unroll
    for (int i = 0; i < 65; i++) {
        float v = acc[i];
        v += __shfl_xor_sync(0xffffffffu, v, 16);
        v += __shfl_xor_sync(0xffffffffu, v, 8);
        v += __shfl_xor_sync(0xffffffffu, v, 4);
        v += __shfl_xor_sync(0xffffffffu, v, 2);
        v += __shfl_xor_sync(0xffffffffu, v, 1);
        acc[i] = v;
    }
    if (lane == 0) {
#pragma unroll
        for (int i = 0; i < 65; i++) sred[warp][i] = acc[i];
    }
    __syncthreads();

    if (threadIdx.x < 65) {
        float s = 0.f;
#pragma unroll
        for (int w = 0; w < 8; w++) s += sred[w][threadIdx.x];
        atomicAdd(&d_stats[threadIdx.x], (double)s);
    }
}

// ---------------- finalize: closed-form BN params per channel ----------------
__global__ void finalize_kernel(const float* __restrict__ W,
                                const float* __restrict__ gamma,
                                const float* __restrict__ beta) {
    int c = threadIdx.x;
    if (c >= NCH) return;

    double A = (double)W[0*NCH+c] + (double)W[4*NCH+c] + (double)W[7*NCH+c];
    double Bv= (double)W[1*NCH+c] + (double)W[5*NCH+c] + (double)W[8*NCH+c];
    double Cv= (double)W[2*NCH+c] + (double)W[6*NCH+c] + (double)W[9*NCH+c];
    double Dv= (double)W[3*NCH+c];
    double u[4] = {A, Bv, Cv, Dv};
    double g[6];
#pragma unroll
    for (int j = 0; j < 6; j++) g[j] = (double)W[(4 + j)*NCH + c];

    double st[65];
#pragma unroll
    for (int i = 0; i < 65; i++) st[i] = d_stats[i];

    double S1 = u[0]*st[0] + u[1]*st[1] + u[2]*st[2] + u[3]*st[3];
    double sg = 0.0;
#pragma unroll
    for (int j = 0; j < 6; j++) sg += g[j] * st[14 + j];
    S1 -= (double)MPTS * sg;

    double Q1 = st[4]*A*A + st[8]*Bv*Bv + st[11]*Cv*Cv + st[13]*Dv*Dv
              + 2.0*(st[5]*A*Bv + st[6]*A*Cv + st[7]*A*Dv
                   + st[9]*Bv*Cv + st[10]*Bv*Dv + st[12]*Cv*Dv);
    double Q2 = 0.0;
#pragma unroll
    for (int i = 0; i < 4; i++)
#pragma unroll
        for (int j = 0; j < 6; j++) Q2 += u[i] * st[20 + i*6 + j] * g[j];
    double Q3 = 0.0;
    {
        int k = 0;
#pragma unroll
        for (int i = 0; i < 6; i++)
#pragma unroll
            for (int j = i; j < 6; j++) {
                Q3 += (i == j ? 1.0 : 2.0) * g[i] * g[j] * st[44 + k];
                k++;
            }
    }
    double S2 = Q1 - 2.0*Q2 + (double)MPTS * Q3;

    double N   = (double)NPIL * (double)MPTS;
    double mu  = S1 / N;
    double var = S2 / N - mu * mu;
    double s   = (double)gamma[c] / sqrt(var + 1e-3);
    double t   = (double)beta[c] - s * mu;

    d_U[c]  = make_float4((float)(s*A), (float)(s*Bv), (float)(s*Cv), (float)(s*Dv));
    d_G0[c] = make_float4((float)(s*g[0]), (float)(s*g[1]), (float)(s*g[2]), (float)(s*g[3]));
    d_G1[c] = make_float4((float)(s*g[4]), (float)(s*g[5]), (float)t, 0.f);
}

// ---------------- bev: gather-style fused zero+compute+write ----------------
// Block = 256 threads, owns CHUNK=128 cells of one batch row.
// Phase 1: read winners, compact.  Phase 2: per-winner 64-ch compute (warp
// parallel, pillar data via L1 broadcast).  Phase 3: coalesced float4 stream
// of all 64 channel rows (zeros + computed values in one pass).
__global__ void __launch_bounds__(256) bev_kernel(const float4* __restrict__ pil4,
                                                  float* __restrict__ out) {
    __shared__ int   s_slot[CHUNK];     // -1 zero, 0..MAXW-1 slot, -2 direct-stored
    __shared__ int2  s_list[CHUNK];     // (cell_local, pillar)
    __shared__ float s_vals[NCH * VPITCH];
    __shared__ int   s_n;

    int t    = threadIdx.x;
    int lane = t & 31;
    int warp = t >> 5;
    int b    = blockIdx.y;
    int c0   = blockIdx.x * CHUNK;
    size_t rowbase = (size_t)b * NCH * NYNX + c0;

    if (t == 0) s_n = 0;
    __syncthreads();

    // --- phase 1: winners ---
    if (t < CHUNK) {
        int w = d_winner[b * NYNX + c0 + t];
        int slot = -1;
        if (w >= 0) {
            slot = atomicAdd(&s_n, 1);
            s_list[slot] = make_int2(t, w);
            if (slot >= MAXW) slot = -2;   // overflow: direct-store path
        }
        s_slot[t] = slot;
    }
    __syncthreads();
    int n = s_n;

    // --- phase 2: compute winner values (each warp strides over slots) ---
    // lane handles channels (lane) and (lane+32)
    if (n > 0) {
        float4 Ua = d_U[lane],       Ub = d_U[lane + 32];
        float4 a0 = d_G0[lane],      b0 = d_G1[lane];
        float4 a1 = d_G0[lane + 32], b1 = d_G1[lane + 32];

        for (int s = warp; s < n; s += 8) {
            int2 e = s_list[s];
            int  p = e.y;
            float4 w0 = d_wbuf4[p*2 + 0];
            float4 w1 = d_wbuf4[p*2 + 1];
            float cst0 = b0.z - (w0.x*a0.x + w0.y*a0.y + w0.z*a0.z
                               + w1.x*a0.w + w1.y*b0.x + w1.z*b0.y);
            float cst1 = b1.z - (w0.x*a1.x + w0.y*a1.y + w0.z*a1.z
                               + w1.x*a1.w + w1.y*b1.x + w1.z*b1.y);

            const float4* vp = pil4 + (size_t)p * MPTS;
            float q0 = -3.4e38f, q1 = -3.4e38f;
#pragma unroll 8
            for (int m = 0; m < MPTS; m++) {
                float4 v = vp[m];
                float d0 = fmaf(v.x, Ua.x, fmaf(v.y, Ua.y, fmaf(v.z, Ua.z, v.w * Ua.w)));
                float d1 = fmaf(v.x, Ub.x, fmaf(v.y, Ub.y, fmaf(v.z, Ub.z, v.w * Ub.w)));
                q0 = fmaxf(q0, d0);
                q1 = fmaxf(q1, d1);
            }
            float r0 = fmaxf(q0 + cst0, 0.0f);
            float r1 = fmaxf(q1 + cst1, 0.0f);

            if (s < MAXW) {
                s_vals[lane * VPITCH + s]        = r0;
                s_vals[(lane + 32) * VPITCH + s] = r1;
            } else {
                // overflow (astronomically rare): direct scattered store
                out[rowbase + (size_t)lane        * NYNX + e.x] = r0;
                out[rowbase + (size_t)(lane + 32) * NYNX + e.x] = r1;
            }
        }
    }
    __syncthreads();

    // --- phase 3: coalesced write-out. warp w handles channels 8w..8w+7 ---
    int4 sl = ((const int4*)s_slot)[lane];   // slots for cells 4*lane..4*lane+3
    int mn = min(min(sl.x, sl.y), min(sl.z, sl.w));
#pragma unroll
    for (int r = 0; r < 8; r++) {
        int ch = warp * 8 + r;
        const float* vrow = &s_vals[ch * VPITCH];
        float4 v;
        v.x = (sl.x >= 0) ? vrow[sl.x] : 0.f;
        v.y = (sl.y >= 0) ? vrow[sl.y] : 0.f;
        v.z = (sl.z >= 0) ? vrow[sl.z] : 0.f;
        v.w = (sl.w >= 0) ? vrow[sl.w] : 0.f;
        float* dst = out + rowbase + (size_t)ch * NYNX + lane * 4;
        if (mn > -2) {
            *(float4*)dst = v;
        } else {  // contains a direct-stored cell: element-wise predicated
            if (sl.x != -2) dst[0] = v.x;
            if (sl.y != -2) dst[1] = v.y;
            if (sl.z != -2) dst[2] = v.z;
            if (sl.w != -2) dst[3] = v.w;
        }
    }
}

// ---------------- launch ----------------
extern "C" void kernel_launch(void* const* d_in, const int* in_sizes, int n_in,
                              void* d_out, int out_size) {
    const float4* pil4    = (const float4*)d_in[0];
    const int4*   coords4 = (const int4*)d_in[1];
    const int*    nump    = (const int*)d_in[2];
    const float*  W       = (const float*)d_in[3];
    const float*  gamma   = (const float*)d_in[4];
    const float*  beta    = (const float*)d_in[5];
    float* out = (float*)d_out;

    pre_init_kernel<<<592, 256>>>();
    stats_kernel<<<(NPIL + 255) / 256, 256>>>(pil4, coords4, nump);
    finalize_kernel<<<1, 64>>>(W, gamma, beta);
    dim3 grid(NCHUNK, BATCH);
    bev_kernel<<<grid, 256>>>(pil4, out);
}

// round 5
// speedup vs baseline: 2.4054x; 1.1638x over previous
#include <cuda_runtime.h>
#include <cstdint>

#define NPIL   96000
#define MPTS   32
#define BATCH  8
#define NXc    432
#define NYc    496
#define NYNX   (NYc*NXc)          /* 214272 */
#define NCH    64
#define WCHUNK 256
#define NWCHUNK (NYNX / WCHUNK)   /* 837 exactly */
#define WMAX   64
#define WPITCH 65

// ---------------- device scratch (static, no allocation) ----------------
__device__ double d_stats[65];
__device__ float4 d_wbuf4[NPIL * 2];          // per pillar: (mx,my,mz,0),(cx,cy,cz,0)
__device__ int    d_winner[BATCH * NYNX];     // 6.9 MB
__device__ float4 d_vals4[NPIL * 16];         // 24.6 MB: per pillar 64 channel values
__device__ float4 d_U[NCH];                   // s * (A,B,C,D)
__device__ float4 d_G0[NCH];                  // s * g[0..3]
__device__ float4 d_G1[NCH];                  // s*g4, s*g5, t, 0

// ---------------- pre-init: winner=-1, stats=0 ----------------
__global__ void pre_init_kernel() {
    int i = blockIdx.x * blockDim.x + threadIdx.x;
    int stride = gridDim.x * blockDim.x;
    const int nw = BATCH * NYNX;
    int4* w4 = (int4*)d_winner;
    int4 m1 = make_int4(-1, -1, -1, -1);
    for (int j = i; j < nw / 4; j += stride) w4[j] = m1;
    if (i < 65) d_stats[i] = 0.0;
}

// ---------------- stats + winner + wbuf: one pass over pillar data ----------------
__global__ void __launch_bounds__(256) stats_kernel(const float4* __restrict__ pil4,
                             const int4*  __restrict__ coords4,
                             const int*   __restrict__ nump) {
    __shared__ float sred[8][65];
    int p = blockIdx.x * blockDim.x + threadIdx.x;
    int lane = threadIdx.x & 31;
    int warp = threadIdx.x >> 5;

    float acc[65];
#pragma unroll
    for (int i = 0; i < 65; i++) acc[i] = 0.f;

    if (p < NPIL) {
        float sx=0.f, sy=0.f, sz=0.f, sw=0.f;
        float xx=0.f,xy=0.f,xz=0.f,xw=0.f,yy=0.f,yz=0.f,yw=0.f,zz=0.f,zw=0.f,ww=0.f;
        const float4* vp = pil4 + (size_t)p * MPTS;
#pragma unroll 8
        for (int m = 0; m < MPTS; m++) {
            float4 v = vp[m];
            sx += v.x; sy += v.y; sz += v.z; sw += v.w;
            xx = fmaf(v.x, v.x, xx); xy = fmaf(v.x, v.y, xy);
            xz = fmaf(v.x, v.z, xz); xw = fmaf(v.x, v.w, xw);
            yy = fmaf(v.y, v.y, yy); yz = fmaf(v.y, v.z, yz);
            yw = fmaf(v.y, v.w, yw);
            zz = fmaf(v.z, v.z, zz); zw = fmaf(v.z, v.w, zw);
            ww = fmaf(v.w, v.w, ww);
        }
        int4 cd = coords4[p];                // (b, z, y, x)

        // winner scatter-order emulation (last index wins)
        int cell = cd.y + cd.z * NXc + cd.w;
        atomicMax(&d_winner[cd.x * NYNX + cell], p);

        float n = (float)nump[p];
        float mx = sx / n, my = sy / n, mz = sz / n;
        float ctrx = (float)cd.w * 0.16f + 0.08f;
        float ctry = (float)cd.z * 0.16f + (-39.6f);
        float ctrz = (float)cd.y * 4.0f  + (-1.0f);

        float sv[4] = {sx, sy, sz, sw};
        float w6[6] = {mx, my, mz, ctrx, ctry, ctrz};

        acc[0]=sx; acc[1]=sy; acc[2]=sz; acc[3]=sw;
        acc[4]=xx; acc[5]=xy; acc[6]=xz; acc[7]=xw; acc[8]=yy;
        acc[9]=yz; acc[10]=yw; acc[11]=zz; acc[12]=zw; acc[13]=ww;
#pragma unroll
        for (int j = 0; j < 6; j++) acc[14 + j] = w6[j];
#pragma unroll
        for (int i = 0; i < 4; i++)
#pragma unroll
            for (int j = 0; j < 6; j++) acc[20 + i*6 + j] = sv[i] * w6[j];
        {
            int k = 0;
#pragma unroll
            for (int i = 0; i < 6; i++)
#pragma unroll
                for (int j = i; j < 6; j++) { acc[44 + k] = w6[i] * w6[j]; k++; }
        }
        d_wbuf4[p*2 + 0] = make_float4(mx, my, mz, 0.f);
        d_wbuf4[p*2 + 1] = make_float4(ctrx, ctry, ctrz, 0.f);
    }

    // warp tree-reduce all 65 partials
#pragma unroll
    for (int i = 0; i < 65; i++) {
        float v = acc[i];
        v += __shfl_xor_sync(0xffffffffu, v, 16);
        v += __shfl_xor_sync(0xffffffffu, v, 8);
        v += __shfl_xor_sync(0xffffffffu, v, 4);
        v += __shfl_xor_sync(0xffffffffu, v, 2);
        v += __shfl_xor_sync(0xffffffffu, v, 1);
        acc[i] = v;
    }
    if (lane == 0) {
#pragma unroll
        for (int i = 0; i < 65; i++) sred[warp][i] = acc[i];
    }
    __syncthreads();

    if (threadIdx.x < 65) {
        float s = 0.f;
#pragma unroll
        for (int w = 0; w < 8; w++) s += sred[w][threadIdx.x];
        atomicAdd(&d_stats[threadIdx.x], (double)s);
    }
}

// ---------------- finalize: closed-form BN params per channel ----------------
__global__ void finalize_kernel(const float* __restrict__ W,
                                const float* __restrict__ gamma,
                                const float* __restrict__ beta) {
    int c = threadIdx.x;
    if (c >= NCH) return;

    double A = (double)W[0*NCH+c] + (double)W[4*NCH+c] + (double)W[7*NCH+c];
    double Bv= (double)W[1*NCH+c] + (double)W[5*NCH+c] + (double)W[8*NCH+c];
    double Cv= (double)W[2*NCH+c] + (double)W[6*NCH+c] + (double)W[9*NCH+c];
    double Dv= (double)W[3*NCH+c];
    double u[4] = {A, Bv, Cv, Dv};
    double g[6];
#pragma unroll
    for (int j = 0; j < 6; j++) g[j] = (double)W[(4 + j)*NCH + c];

    double st[65];
#pragma unroll
    for (int i = 0; i < 65; i++) st[i] = d_stats[i];

    double S1 = u[0]*st[0] + u[1]*st[1] + u[2]*st[2] + u[3]*st[3];
    double sg = 0.0;
#pragma unroll
    for (int j = 0; j < 6; j++) sg += g[j] * st[14 + j];
    S1 -= (double)MPTS * sg;

    double Q1 = st[4]*A*A + st[8]*Bv*Bv + st[11]*Cv*Cv + st[13]*Dv*Dv
              + 2.0*(st[5]*A*Bv + st[6]*A*Cv + st[7]*A*Dv
                   + st[9]*Bv*Cv + st[10]*Bv*Dv + st[12]*Cv*Dv);
    double Q2 = 0.0;
#pragma unroll
    for (int i = 0; i < 4; i++)
#pragma unroll
        for (int j = 0; j < 6; j++) Q2 += u[i] * st[20 + i*6 + j] * g[j];
    double Q3 = 0.0;
    {
        int k = 0;
#pragma unroll
        for (int i = 0; i < 6; i++)
#pragma unroll
            for (int j = i; j < 6; j++) {
                Q3 += (i == j ? 1.0 : 2.0) * g[i] * g[j] * st[44 + k];
                k++;
            }
    }
    double S2 = Q1 - 2.0*Q2 + (double)MPTS * Q3;

    double N   = (double)NPIL * (double)MPTS;
    double mu  = S1 / N;
    double var = S2 / N - mu * mu;
    double s   = (double)gamma[c] / sqrt(var + 1e-3);
    double t   = (double)beta[c] - s * mu;

    d_U[c]  = make_float4((float)(s*A), (float)(s*Bv), (float)(s*Cv), (float)(s*Dv));
    d_G0[c] = make_float4((float)(s*g[0]), (float)(s*g[1]), (float)(s*g[2]), (float)(s*g[3]));
    d_G1[c] = make_float4((float)(s*g[4]), (float)(s*g[5]), (float)t, 0.f);
}

// ---------------- vals: packed-f32x2 GEMM + BN + relu + maxpool, compact store ----------------
__global__ void __launch_bounds__(256) vals_kernel(const float4* __restrict__ pil4) {
    // packed point-pair layout per pillar: 16 pairs x 32B
    __shared__ float spack[4][128];

    int tid = threadIdx.x;
    int pi  = tid >> 6;          // pillar slot 0..3
    int c   = tid & 63;          // channel
    int pbase = blockIdx.x * 4;
    int p = pbase + pi;

    if (tid < 128) {
        int lp = tid >> 5;
        int m  = tid & 31;
        float4 v = pil4[(size_t)(pbase + lp) * MPTS + m];
        float* sp = &spack[lp][(m >> 1) * 8 + (m & 1)];
        sp[0] = v.x; sp[2] = v.y; sp[4] = v.z; sp[6] = v.w;
    }

    float4 U = d_U[c];
    float4 a = d_G0[c];
    float4 b = d_G1[c];
    float4 w0 = d_wbuf4[p*2 + 0];
    float4 w1 = d_wbuf4[p*2 + 1];

    __syncthreads();

    float cst = b.z - (w0.x*a.x + w0.y*a.y + w0.z*a.z
                     + w1.x*a.w + w1.y*b.x + w1.z*b.y);

    unsigned long long Ux2, Uy2, Uz2, Uw2;
    asm("mov.b64 %0, {%1,%1};" : "=l"(Ux2) : "f"(U.x));
    asm("mov.b64 %0, {%1,%1};" : "=l"(Uy2) : "f"(U.y));
    asm("mov.b64 %0, {%1,%1};" : "=l"(Uz2) : "f"(U.z));
    asm("mov.b64 %0, {%1,%1};" : "=l"(Uw2) : "f"(U.w));

    const ulonglong2* sp2 = (const ulonglong2*)&spack[pi][0];

    float q0 = -3.4e38f, q1 = -3.4e38f;
#pragma unroll
    for (int j = 0; j < 16; j++) {
        ulonglong2 P0 = sp2[j*2 + 0];    // {vx2, vy2}
        ulonglong2 P1 = sp2[j*2 + 1];    // {vz2, vw2}
        unsigned long long d;
        asm("mul.rn.f32x2 %0, %1, %2;"     : "=l"(d) : "l"(P1.y), "l"(Uw2));
        asm("fma.rn.f32x2 %0, %1, %2, %0;" : "+l"(d) : "l"(P1.x), "l"(Uz2));
        asm("fma.rn.f32x2 %0, %1, %2, %0;" : "+l"(d) : "l"(P0.y), "l"(Uy2));
        asm("fma.rn.f32x2 %0, %1, %2, %0;" : "+l"(d) : "l"(P0.x), "l"(Ux2));
        float lo, hi;
        asm("mov.b64 {%0,%1}, %2;" : "=f"(lo), "=f"(hi) : "l"(d));
        q0 = fmaxf(q0, lo);
        q1 = fmaxf(q1, hi);
    }
    float val = fmaxf(fmaxf(q0, q1) + cst, 0.0f);

    ((float*)d_vals4)[p * NCH + c] = val;   // coalesced 256B per pillar
}

// ---------------- writer: pure streaming gather -> coalesced output ----------------
__global__ void __launch_bounds__(256) writer_kernel(float* __restrict__ out) {
    __shared__ int   s_slot[WCHUNK];    // -1 zero, 0..WMAX-1 slot, -2 direct-stored
    __shared__ int2  s_list[WCHUNK];    // (cell_local, pillar)
    __shared__ float s_vals[NCH * WPITCH];
    __shared__ int   s_n;

    int t    = threadIdx.x;
    int lane = t & 31;
    int warp = t >> 5;
    int b    = blockIdx.y;
    int c0   = blockIdx.x * WCHUNK;
    size_t rowbase = (size_t)b * NCH * NYNX + c0;

    if (t == 0) s_n = 0;
    __syncthreads();

    // --- phase 1: winners (coalesced) ---
    {
        int w = d_winner[b * NYNX + c0 + t];
        int slot = -1;
        if (w >= 0) {
            slot = atomicAdd(&s_n, 1);
            s_list[slot] = make_int2(t, w);
            if (slot >= WMAX) slot = -2;
        }
        s_slot[t] = slot;
    }
    __syncthreads();
    int n = s_n;

    // --- phase 2: gather vals rows (256B contiguous per winner, L2-resident) ---
    for (int idx = t; idx < n * 16; idx += 256) {
        int s = idx >> 4;
        int j = idx & 15;
        int2 e = s_list[s];
        float4 v = d_vals4[(size_t)e.y * 16 + j];
        if (s < WMAX) {
            s_vals[(4*j + 0) * WPITCH + s] = v.x;
            s_vals[(4*j + 1) * WPITCH + s] = v.y;
            s_vals[(4*j + 2) * WPITCH + s] = v.z;
            s_vals[(4*j + 3) * WPITCH + s] = v.w;
        } else {
            // overflow (astronomically rare): direct scattered store
            out[rowbase + (size_t)(4*j + 0) * NYNX + e.x] = v.x;
            out[rowbase + (size_t)(4*j + 1) * NYNX + e.x] = v.y;
            out[rowbase + (size_t)(4*j + 2) * NYNX + e.x] = v.z;
            out[rowbase + (size_t)(4*j + 3) * NYNX + e.x] = v.w;
        }
    }
    __syncthreads();

    // --- phase 3: stream all 64 channel rows. warp w -> channels 8w..8w+7 ---
    int4 sl0 = ((const int4*)s_slot)[lane];        // cells 4*lane .. 4*lane+3
    int4 sl1 = ((const int4*)s_slot)[lane + 32];   // cells 128+4*lane ..
    int mn0 = min(min(sl0.x, sl0.y), min(sl0.z, sl0.w));
    int mn1 = min(min(sl1.x, sl1.y), min(sl1.z, sl1.w));
#pragma unroll
    for (int r = 0; r < 8; r++) {
        int ch = warp * 8 + r;
        const float* vrow = &s_vals[ch * WPITCH];
        float* dst = out + rowbase + (size_t)ch * NYNX;

        float4 v0;
        v0.x = (sl0.x >= 0) ? vrow[sl0.x] : 0.f;
        v0.y = (sl0.y >= 0) ? vrow[sl0.y] : 0.f;
        v0.z = (sl0.z >= 0) ? vrow[sl0.z] : 0.f;
        v0.w = (sl0.w >= 0) ? vrow[sl0.w] : 0.f;
        if (mn0 > -2) {
            __stcs((float4*)(dst + lane * 4), v0);
        } else {
            if (sl0.x != -2) dst[lane*4 + 0] = v0.x;
            if (sl0.y != -2) dst[lane*4 + 1] = v0.y;
            if (sl0.z != -2) dst[lane*4 + 2] = v0.z;
            if (sl0.w != -2) dst[lane*4 + 3] = v0.w;
        }

        float4 v1;
        v1.x = (sl1.x >= 0) ? vrow[sl1.x] : 0.f;
        v1.y = (sl1.y >= 0) ? vrow[sl1.y] : 0.f;
        v1.z = (sl1.z >= 0) ? vrow[sl1.z] : 0.f;
        v1.w = (sl1.w >= 0) ? vrow[sl1.w] : 0.f;
        if (mn1 > -2) {
            __stcs((float4*)(dst + 128 + lane * 4), v1);
        } else {
            if (sl1.x != -2) dst[128 + lane*4 + 0] = v1.x;
            if (sl1.y != -2) dst[128 + lane*4 + 1] = v1.y;
            if (sl1.z != -2) dst[128 + lane*4 + 2] = v1.z;
            if (sl1.w != -2) dst[128 + lane*4 + 3] = v1.w;
        }
    }
}

// ---------------- launch ----------------
extern "C" void kernel_launch(void* const* d_in, const int* in_sizes, int n_in,
                              void* d_out, int out_size) {
    const float4* pil4    = (const float4*)d_in[0];
    const int4*   coords4 = (const int4*)d_in[1];
    const int*    nump    = (const int*)d_in[2];
    const float*  W       = (const float*)d_in[3];
    const float*  gamma   = (const float*)d_in[4];
    const float*  beta    = (const float*)d_in[5];
    float* out = (float*)d_out;

    pre_init_kernel<<<592, 256>>>();
    stats_kernel<<<(NPIL + 255) / 256, 256>>>(pil4, coords4, nump);
    finalize_kernel<<<1, 64>>>(W, gamma, beta);
    vals_kernel<<<NPIL / 4, 256>>>(pil4);
    dim3 grid(NWCHUNK, BATCH);
    writer_kernel<<<grid, 256>>>(out);
}

// round 6
// speedup vs baseline: 2.5609x; 1.0646x over previous
#include <cuda_runtime.h>
#include <cstdint>

#define NPIL   96000
#define MPTS   32
#define BATCH  8
#define NXc    432
#define NYc    496
#define NYNX   (NYc*NXc)          /* 214272 */
#define NCH    64
#define WCHUNK 256
#define NWCHUNK (NYNX / WCHUNK)   /* 837 exactly */
#define WMAX   64
#define WPITCH 65
#define SPITCH 132                /* pillar pitch in floats (bank-skewed) */

// ---------------- device scratch (static, no allocation) ----------------
__device__ double d_stats[65];
__device__ float4 d_wbuf4[NPIL * 2];          // per pillar: (mx,my,mz,0),(cx,cy,cz,0)
__device__ int    d_winner[BATCH * NYNX];     // 6.9 MB
__device__ float4 d_vals4[NPIL * 16];         // 24.6 MB: per pillar 64 channel values
__device__ float4 d_U[NCH];                   // s * (A,B,C,D)
__device__ float4 d_G0[NCH];                  // s * g[0..3]
__device__ float4 d_G1[NCH];                  // s*g4, s*g5, t, 0

// ---------------- pre-init: winner=-1, stats=0 ----------------
__global__ void pre_init_kernel() {
    int i = blockIdx.x * blockDim.x + threadIdx.x;
    int stride = gridDim.x * blockDim.x;
    const int nw = BATCH * NYNX;
    int4* w4 = (int4*)d_winner;
    int4 m1 = make_int4(-1, -1, -1, -1);
    for (int j = i; j < nw / 4; j += stride) w4[j] = m1;
    if (i < 65) d_stats[i] = 0.0;
}

// ---------------- stats + winner + wbuf: one pass over pillar data ----------------
__global__ void __launch_bounds__(256) stats_kernel(const float4* __restrict__ pil4,
                             const int4*  __restrict__ coords4,
                             const int*   __restrict__ nump) {
    __shared__ float sred[8][65];
    int p = blockIdx.x * blockDim.x + threadIdx.x;
    int lane = threadIdx.x & 31;
    int warp = threadIdx.x >> 5;

    float acc[65];
#pragma unroll
    for (int i = 0; i < 65; i++) acc[i] = 0.f;

    if (p < NPIL) {
        float sx=0.f, sy=0.f, sz=0.f, sw=0.f;
        float xx=0.f,xy=0.f,xz=0.f,xw=0.f,yy=0.f,yz=0.f,yw=0.f,zz=0.f,zw=0.f,ww=0.f;
        const float4* vp = pil4 + (size_t)p * MPTS;
#pragma unroll 8
        for (int m = 0; m < MPTS; m++) {
            float4 v = vp[m];
            sx += v.x; sy += v.y; sz += v.z; sw += v.w;
            xx = fmaf(v.x, v.x, xx); xy = fmaf(v.x, v.y, xy);
            xz = fmaf(v.x, v.z, xz); xw = fmaf(v.x, v.w, xw);
            yy = fmaf(v.y, v.y, yy); yz = fmaf(v.y, v.z, yz);
            yw = fmaf(v.y, v.w, yw);
            zz = fmaf(v.z, v.z, zz); zw = fmaf(v.z, v.w, zw);
            ww = fmaf(v.w, v.w, ww);
        }
        int4 cd = coords4[p];                // (b, z, y, x)

        // winner scatter-order emulation (last index wins)
        int cell = cd.y + cd.z * NXc + cd.w;
        atomicMax(&d_winner[cd.x * NYNX + cell], p);

        float n = (float)nump[p];
        float mx = sx / n, my = sy / n, mz = sz / n;
        float ctrx = (float)cd.w * 0.16f + 0.08f;
        float ctry = (float)cd.z * 0.16f + (-39.6f);
        float ctrz = (float)cd.y * 4.0f  + (-1.0f);

        float sv[4] = {sx, sy, sz, sw};
        float w6[6] = {mx, my, mz, ctrx, ctry, ctrz};

        acc[0]=sx; acc[1]=sy; acc[2]=sz; acc[3]=sw;
        acc[4]=xx; acc[5]=xy; acc[6]=xz; acc[7]=xw; acc[8]=yy;
        acc[9]=yz; acc[10]=yw; acc[11]=zz; acc[12]=zw; acc[13]=ww;
#pragma unroll
        for (int j = 0; j < 6; j++) acc[14 + j] = w6[j];
#pragma unroll
        for (int i = 0; i < 4; i++)
#pragma unroll
            for (int j = 0; j < 6; j++) acc[20 + i*6 + j] = sv[i] * w6[j];
        {
            int k = 0;
#pragma unroll
            for (int i = 0; i < 6; i++)
#pragma unroll
                for (int j = i; j < 6; j++) { acc[44 + k] = w6[i] * w6[j]; k++; }
        }
        d_wbuf4[p*2 + 0] = make_float4(mx, my, mz, 0.f);
        d_wbuf4[p*2 + 1] = make_float4(ctrx, ctry, ctrz, 0.f);
    }

    // warp tree-reduce all 65 partials
#pragma unroll
    for (int i = 0; i < 65; i++) {
        float v = acc[i];
        v += __shfl_xor_sync(0xffffffffu, v, 16);
        v += __shfl_xor_sync(0xffffffffu, v, 8);
        v += __shfl_xor_sync(0xffffffffu, v, 4);
        v += __shfl_xor_sync(0xffffffffu, v, 2);
        v += __shfl_xor_sync(0xffffffffu, v, 1);
        acc[i] = v;
    }
    if (lane == 0) {
#pragma unroll
        for (int i = 0; i < 65; i++) sred[warp][i] = acc[i];
    }
    __syncthreads();

    if (threadIdx.x < 65) {
        float s = 0.f;
#pragma unroll
        for (int w = 0; w < 8; w++) s += sred[w][threadIdx.x];
        atomicAdd(&d_stats[threadIdx.x], (double)s);
    }
}

// ---------------- finalize: closed-form BN params per channel ----------------
__global__ void finalize_kernel(const float* __restrict__ W,
                                const float* __restrict__ gamma,
                                const float* __restrict__ beta) {
    int c = threadIdx.x;
    if (c >= NCH) return;

    double A = (double)W[0*NCH+c] + (double)W[4*NCH+c] + (double)W[7*NCH+c];
    double Bv= (double)W[1*NCH+c] + (double)W[5*NCH+c] + (double)W[8*NCH+c];
    double Cv= (double)W[2*NCH+c] + (double)W[6*NCH+c] + (double)W[9*NCH+c];
    double Dv= (double)W[3*NCH+c];
    double u[4] = {A, Bv, Cv, Dv};
    double g[6];
#pragma unroll
    for (int j = 0; j < 6; j++) g[j] = (double)W[(4 + j)*NCH + c];

    double st[65];
#pragma unroll
    for (int i = 0; i < 65; i++) st[i] = d_stats[i];

    double S1 = u[0]*st[0] + u[1]*st[1] + u[2]*st[2] + u[3]*st[3];
    double sg = 0.0;
#pragma unroll
    for (int j = 0; j < 6; j++) sg += g[j] * st[14 + j];
    S1 -= (double)MPTS * sg;

    double Q1 = st[4]*A*A + st[8]*Bv*Bv + st[11]*Cv*Cv + st[13]*Dv*Dv
              + 2.0*(st[5]*A*Bv + st[6]*A*Cv + st[7]*A*Dv
                   + st[9]*Bv*Cv + st[10]*Bv*Dv + st[12]*Cv*Dv);
    double Q2 = 0.0;
#pragma unroll
    for (int i = 0; i < 4; i++)
#pragma unroll
        for (int j = 0; j < 6; j++) Q2 += u[i] * st[20 + i*6 + j] * g[j];
    double Q3 = 0.0;
    {
        int k = 0;
#pragma unroll
        for (int i = 0; i < 6; i++)
#pragma unroll
            for (int j = i; j < 6; j++) {
                Q3 += (i == j ? 1.0 : 2.0) * g[i] * g[j] * st[44 + k];
                k++;
            }
    }
    double S2 = Q1 - 2.0*Q2 + (double)MPTS * Q3;

    double N   = (double)NPIL * (double)MPTS;
    double mu  = S1 / N;
    double var = S2 / N - mu * mu;
    double s   = (double)gamma[c] / sqrt(var + 1e-3);
    double t   = (double)beta[c] - s * mu;

    d_U[c]  = make_float4((float)(s*A), (float)(s*Bv), (float)(s*Cv), (float)(s*Dv));
    d_G0[c] = make_float4((float)(s*g[0]), (float)(s*g[1]), (float)(s*g[2]), (float)(s*g[3]));
    d_G1[c] = make_float4((float)(s*g[4]), (float)(s*g[5]), (float)t, 0.f);
}

// ---------------- vals: 16 threads/pillar x 4 channels, packed f32x2 ----------------
__global__ void __launch_bounds__(256) vals_kernel(const float4* __restrict__ pil4) {
    // 16 pillars per block; pair-packed layout per pillar, pitch 132 floats:
    //   pair j at [j*8]: x2j x2j+1 y2j y2j+1 z2j z2j+1 w2j w2j+1
    __shared__ float spack[16 * SPITCH];

    int tid = threadIdx.x;
    int pg  = tid >> 4;          // pillar slot 0..15
    int g   = tid & 15;          // channel group: channels 4g..4g+3
    int pbase = blockIdx.x * 16;
    int p = pbase + pg;

    // load 16 pillars (512 float4) with 256 threads
#pragma unroll
    for (int k = 0; k < 2; k++) {
        int idx = tid + k * 256;
        int lp = idx >> 5;
        int m  = idx & 31;
        float4 v = pil4[(size_t)(pbase + lp) * MPTS + m];
        float* sp = &spack[lp * SPITCH + (m >> 1) * 8 + (m & 1)];
        sp[0] = v.x; sp[2] = v.y; sp[4] = v.z; sp[6] = v.w;
    }

    // per-thread: 4 channels of weights, splatted to f32x2
    unsigned long long Ux2[4], Uy2[4], Uz2[4], Uw2[4];
    float cst[4];
    {
        float4 w0 = d_wbuf4[p*2 + 0];
        float4 w1 = d_wbuf4[p*2 + 1];
#pragma unroll
        for (int k = 0; k < 4; k++) {
            int c = 4 * g + k;
            float4 U = d_U[c];
            float4 a = d_G0[c];
            float4 b = d_G1[c];
            cst[k] = b.z - (w0.x*a.x + w0.y*a.y + w0.z*a.z
                          + w1.x*a.w + w1.y*b.x + w1.z*b.y);
            asm("mov.b64 %0, {%1,%1};" : "=l"(Ux2[k]) : "f"(U.x));
            asm("mov.b64 %0, {%1,%1};" : "=l"(Uy2[k]) : "f"(U.y));
            asm("mov.b64 %0, {%1,%1};" : "=l"(Uz2[k]) : "f"(U.z));
            asm("mov.b64 %0, {%1,%1};" : "=l"(Uw2[k]) : "f"(U.w));
        }
    }

    __syncthreads();

    const ulonglong2* sp2 = (const ulonglong2*)&spack[pg * SPITCH];

    float q0[4], q1[4];
#pragma unroll
    for (int k = 0; k < 4; k++) { q0[k] = -3.4e38f; q1[k] = -3.4e38f; }

#pragma unroll
    for (int j = 0; j < 16; j++) {
        ulonglong2 P0 = sp2[j*2 + 0];    // {x2, y2}
        ulonglong2 P1 = sp2[j*2 + 1];    // {z2, w2}
#pragma unroll
        for (int k = 0; k < 4; k++) {
            unsigned long long d;
            asm("mul.rn.f32x2 %0, %1, %2;"     : "=l"(d) : "l"(P1.y), "l"(Uw2[k]));
            asm("fma.rn.f32x2 %0, %1, %2, %0;" : "+l"(d) : "l"(P1.x), "l"(Uz2[k]));
            asm("fma.rn.f32x2 %0, %1, %2, %0;" : "+l"(d) : "l"(P0.y), "l"(Uy2[k]));
            asm("fma.rn.f32x2 %0, %1, %2, %0;" : "+l"(d) : "l"(P0.x), "l"(Ux2[k]));
            float lo, hi;
            asm("mov.b64 {%0,%1}, %2;" : "=f"(lo), "=f"(hi) : "l"(d));
            q0[k] = fmaxf(q0[k], lo);
            q1[k] = fmaxf(q1[k], hi);
        }
    }

    float4 res;
    res.x = fmaxf(fmaxf(q0[0], q1[0]) + cst[0], 0.0f);
    res.y = fmaxf(fmaxf(q0[1], q1[1]) + cst[1], 0.0f);
    res.z = fmaxf(fmaxf(q0[2], q1[2]) + cst[2], 0.0f);
    res.w = fmaxf(fmaxf(q0[3], q1[3]) + cst[3], 0.0f);

    d_vals4[(size_t)p * 16 + g] = res;   // 16 threads -> 256B coalesced
}

// ---------------- writer: pure streaming gather -> coalesced output ----------------
__global__ void __launch_bounds__(256) writer_kernel(float* __restrict__ out) {
    __shared__ int   s_slot[WCHUNK];    // -1 zero, 0..WMAX-1 slot, -2 direct-stored
    __shared__ int2  s_list[WCHUNK];    // (cell_local, pillar)
    __shared__ float s_vals[NCH * WPITCH];
    __shared__ int   s_n;

    int t    = threadIdx.x;
    int lane = t & 31;
    int warp = t >> 5;
    int b    = blockIdx.y;
    int c0   = blockIdx.x * WCHUNK;
    size_t rowbase = (size_t)b * NCH * NYNX + c0;

    if (t == 0) s_n = 0;
    __syncthreads();

    // --- phase 1: winners (coalesced) ---
    {
        int w = d_winner[b * NYNX + c0 + t];
        int slot = -1;
        if (w >= 0) {
            slot = atomicAdd(&s_n, 1);
            s_list[slot] = make_int2(t, w);
            if (slot >= WMAX) slot = -2;
        }
        s_slot[t] = slot;
    }
    __syncthreads();
    int n = s_n;

    // --- phase 2: gather vals rows (256B contiguous per winner, L2-resident) ---
    for (int idx = t; idx < n * 16; idx += 256) {
        int s = idx >> 4;
        int j = idx & 15;
        int2 e = s_list[s];
        float4 v = d_vals4[(size_t)e.y * 16 + j];
        if (s < WMAX) {
            s_vals[(4*j + 0) * WPITCH + s] = v.x;
            s_vals[(4*j + 1) * WPITCH + s] = v.y;
            s_vals[(4*j + 2) * WPITCH + s] = v.z;
            s_vals[(4*j + 3) * WPITCH + s] = v.w;
        } else {
            // overflow (astronomically rare): direct scattered store
            out[rowbase + (size_t)(4*j + 0) * NYNX + e.x] = v.x;
            out[rowbase + (size_t)(4*j + 1) * NYNX + e.x] = v.y;
            out[rowbase + (size_t)(4*j + 2) * NYNX + e.x] = v.z;
            out[rowbase + (size_t)(4*j + 3) * NYNX + e.x] = v.w;
        }
    }
    __syncthreads();

    // --- phase 3: stream all 64 channel rows. warp w -> channels 8w..8w+7 ---
    int4 sl0 = ((const int4*)s_slot)[lane];        // cells 4*lane .. 4*lane+3
    int4 sl1 = ((const int4*)s_slot)[lane + 32];   // cells 128+4*lane ..
    int mn0 = min(min(sl0.x, sl0.y), min(sl0.z, sl0.w));
    int mn1 = min(min(sl1.x, sl1.y), min(sl1.z, sl1.w));
#pragma unroll
    for (int r = 0; r < 8; r++) {
        int ch = warp * 8 + r;
        const float* vrow = &s_vals[ch * WPITCH];
        float* dst = out + rowbase + (size_t)ch * NYNX;

        float4 v0;
        v0.x = (sl0.x >= 0) ? vrow[sl0.x] : 0.f;
        v0.y = (sl0.y >= 0) ? vrow[sl0.y] : 0.f;
        v0.z = (sl0.z >= 0) ? vrow[sl0.z] : 0.f;
        v0.w = (sl0.w >= 0) ? vrow[sl0.w] : 0.f;
        if (mn0 > -2) {
            __stcs((float4*)(dst + lane * 4), v0);
        } else {
            if (sl0.x != -2) dst[lane*4 + 0] = v0.x;
            if (sl0.y != -2) dst[lane*4 + 1] = v0.y;
            if (sl0.z != -2) dst[lane*4 + 2] = v0.z;
            if (sl0.w != -2) dst[lane*4 + 3] = v0.w;
        }

        float4 v1;
        v1.x = (sl1.x >= 0) ? vrow[sl1.x] : 0.f;
        v1.y = (sl1.y >= 0) ? vrow[sl1.y] : 0.f;
        v1.z = (sl1.z >= 0) ? vrow[sl1.z] : 0.f;
        v1.w = (sl1.w >= 0) ? vrow[sl1.w] : 0.f;
        if (mn1 > -2) {
            __stcs((float4*)(dst + 128 + lane * 4), v1);
        } else {
            if (sl1.x != -2) dst[128 + lane*4 + 0] = v1.x;
            if (sl1.y != -2) dst[128 + lane*4 + 1] = v1.y;
            if (sl1.z != -2) dst[128 + lane*4 + 2] = v1.z;
            if (sl1.w != -2) dst[128 + lane*4 + 3] = v1.w;
        }
    }
}

// ---------------- launch ----------------
extern "C" void kernel_launch(void* const* d_in, const int* in_sizes, int n_in,
                              void* d_out, int out_size) {
    const float4* pil4    = (const float4*)d_in[0];
    const int4*   coords4 = (const int4*)d_in[1];
    const int*    nump    = (const int*)d_in[2];
    const float*  W       = (const float*)d_in[3];
    const float*  gamma   = (const float*)d_in[4];
    const float*  beta    = (const float*)d_in[5];
    float* out = (float*)d_out;

    pre_init_kernel<<<592, 256>>>();
    stats_kernel<<<(NPIL + 255) / 256, 256>>>(pil4, coords4, nump);
    finalize_kernel<<<1, 64>>>(W, gamma, beta);
    vals_kernel<<<NPIL / 16, 256>>>(pil4);
    dim3 grid(NWCHUNK, BATCH);
    writer_kernel<<<grid, 256>>>(out);
}

// round 8
// speedup vs baseline: 2.8162x; 1.0997x over previous
#include <cuda_runtime.h>
#include <cstdint>

#define NPIL   96000
#define MPTS   32
#define BATCH  8
#define NXc    432
#define NYc    496
#define NYNX   (NYc*NXc)          /* 214272 */
#define NCH    64
#define WCHUNK 256
#define NWCHUNK (NYNX / WCHUNK)   /* 837 exactly */
#define WMAX   64
#define WPITCH 65

// ---------------- device scratch (static, no allocation) ----------------
__device__ double d_stats[65];
__device__ float4 d_wbuf4[NPIL * 2];          // per pillar: (mx,my,mz,0),(cx,cy,cz,0)
__device__ int    d_winner[BATCH * NYNX];     // 6.9 MB
__device__ float4 d_vals4[NPIL * 16];         // 24.6 MB: per pillar 64 channel values
__device__ unsigned long long d_UPK[32 * 4];  // channel-pair packed s*u (A,B,C,D)
__device__ unsigned long long d_GPK[32 * 7];  // channel-pair packed s*g0..g5, t

// ---------------- f32x2 helpers ----------------
__device__ __forceinline__ unsigned long long splat2(float v) {
    unsigned long long r;
    asm("mov.b64 %0, {%1,%1};" : "=l"(r) : "f"(v));
    return r;
}
__device__ __forceinline__ unsigned long long pack2(float lo, float hi) {
    unsigned long long r;
    asm("mov.b64 %0, {%1,%2};" : "=l"(r) : "f"(lo), "f"(hi));
    return r;
}
#define FMA2(d, a, b)  asm("fma.rn.f32x2 %0, %1, %2, %0;" : "+l"(d) : "l"(a), "l"(b))
#define MUL2(d, a, b)  asm("mul.rn.f32x2 %0, %1, %2;"     : "=l"(d) : "l"(a), "l"(b))
#define UNPK2(lo, hi, d) asm("mov.b64 {%0,%1}, %2;" : "=f"(lo), "=f"(hi) : "l"(d))

// ---------------- pre-init: winner=-1, stats=0 ----------------
__global__ void pre_init_kernel() {
    int i = blockIdx.x * blockDim.x + threadIdx.x;
    int stride = gridDim.x * blockDim.x;
    const int nw = BATCH * NYNX;
    int4* w4 = (int4*)d_winner;
    int4 m1 = make_int4(-1, -1, -1, -1);
    for (int j = i; j < nw / 4; j += stride) w4[j] = m1;
    if (i < 65) d_stats[i] = 0.0;
}

// ---------------- stats + winner + wbuf: one pass over pillar data ----------------
__global__ void __launch_bounds__(256) stats_kernel(const float4* __restrict__ pil4,
                             const int4*  __restrict__ coords4,
                             const int*   __restrict__ nump) {
    __shared__ float sred[8][65];
    int p = blockIdx.x * blockDim.x + threadIdx.x;
    int lane = threadIdx.x & 31;
    int warp = threadIdx.x >> 5;

    float acc[65];
#pragma unroll
    for (int i = 0; i < 65; i++) acc[i] = 0.f;

    if (p < NPIL) {
        float sx=0.f, sy=0.f, sz=0.f, sw=0.f;
        float xx=0.f,xy=0.f,xz=0.f,xw=0.f,yy=0.f,yz=0.f,yw=0.f,zz=0.f,zw=0.f,ww=0.f;
        const float4* vp = pil4 + (size_t)p * MPTS;
#pragma unroll 8
        for (int m = 0; m < MPTS; m++) {
            float4 v = vp[m];
            sx += v.x; sy += v.y; sz += v.z; sw += v.w;
            xx = fmaf(v.x, v.x, xx); xy = fmaf(v.x, v.y, xy);
            xz = fmaf(v.x, v.z, xz); xw = fmaf(v.x, v.w, xw);
            yy = fmaf(v.y, v.y, yy); yz = fmaf(v.y, v.z, yz);
            yw = fmaf(v.y, v.w, yw);
            zz = fmaf(v.z, v.z, zz); zw = fmaf(v.z, v.w, zw);
            ww = fmaf(v.w, v.w, ww);
        }
        int4 cd = coords4[p];                // (b, z, y, x)

        // winner scatter-order emulation (last index wins)
        int cell = cd.y + cd.z * NXc + cd.w;
        atomicMax(&d_winner[cd.x * NYNX + cell], p);

        float n = (float)nump[p];
        float mx = sx / n, my = sy / n, mz = sz / n;
        float ctrx = (float)cd.w * 0.16f + 0.08f;
        float ctry = (float)cd.z * 0.16f + (-39.6f);
        float ctrz = (float)cd.y * 4.0f  + (-1.0f);

        float sv[4] = {sx, sy, sz, sw};
        float w6[6] = {mx, my, mz, ctrx, ctry, ctrz};

        acc[0]=sx; acc[1]=sy; acc[2]=sz; acc[3]=sw;
        acc[4]=xx; acc[5]=xy; acc[6]=xz; acc[7]=xw; acc[8]=yy;
        acc[9]=yz; acc[10]=yw; acc[11]=zz; acc[12]=zw; acc[13]=ww;
#pragma unroll
        for (int j = 0; j < 6; j++) acc[14 + j] = w6[j];
#pragma unroll
        for (int i = 0; i < 4; i++)
#pragma unroll
            for (int j = 0; j < 6; j++) acc[20 + i*6 + j] = sv[i] * w6[j];
        {
            int k = 0;
#pragma unroll
            for (int i = 0; i < 6; i++)
#pragma unroll
                for (int j = i; j < 6; j++) { acc[44 + k] = w6[i] * w6[j]; k++; }
        }
        d_wbuf4[p*2 + 0] = make_float4(mx, my, mz, 0.f);
        d_wbuf4[p*2 + 1] = make_float4(ctrx, ctry, ctrz, 0.f);
    }

    // warp tree-reduce all 65 partials
#pragma unroll
    for (int i = 0; i < 65; i++) {
        float v = acc[i];
        v += __shfl_xor_sync(0xffffffffu, v, 16);
        v += __shfl_xor_sync(0xffffffffu, v, 8);
        v += __shfl_xor_sync(0xffffffffu, v, 4);
        v += __shfl_xor_sync(0xffffffffu, v, 2);
        v += __shfl_xor_sync(0xffffffffu, v, 1);
        acc[i] = v;
    }
    if (lane == 0) {
#pragma unroll
        for (int i = 0; i < 65; i++) sred[warp][i] = acc[i];
    }
    __syncthreads();

    if (threadIdx.x < 65) {
        float s = 0.f;
#pragma unroll
        for (int w = 0; w < 8; w++) s += sred[w][threadIdx.x];
        atomicAdd(&d_stats[threadIdx.x], (double)s);
    }
}

// ---------------- finalize: closed-form BN params, channel-pair packed ----------------
__global__ void finalize_kernel(const float* __restrict__ W,
                                const float* __restrict__ gamma,
                                const float* __restrict__ beta) {
    __shared__ float s_u[NCH][4];
    __shared__ float s_g[NCH][6];
    __shared__ float s_t[NCH];

    int c = threadIdx.x;
    if (c < NCH) {
        double A = (double)W[0*NCH+c] + (double)W[4*NCH+c] + (double)W[7*NCH+c];
        double Bv= (double)W[1*NCH+c] + (double)W[5*NCH+c] + (double)W[8*NCH+c];
        double Cv= (double)W[2*NCH+c] + (double)W[6*NCH+c] + (double)W[9*NCH+c];
        double Dv= (double)W[3*NCH+c];
        double u[4] = {A, Bv, Cv, Dv};
        double g[6];
#pragma unroll
        for (int j = 0; j < 6; j++) g[j] = (double)W[(4 + j)*NCH + c];

        double st[65];
#pragma unroll
        for (int i = 0; i < 65; i++) st[i] = d_stats[i];

        double S1 = u[0]*st[0] + u[1]*st[1] + u[2]*st[2] + u[3]*st[3];
        double sg = 0.0;
#pragma unroll
        for (int j = 0; j < 6; j++) sg += g[j] * st[14 + j];
        S1 -= (double)MPTS * sg;

        double Q1 = st[4]*A*A + st[8]*Bv*Bv + st[11]*Cv*Cv + st[13]*Dv*Dv
                  + 2.0*(st[5]*A*Bv + st[6]*A*Cv + st[7]*A*Dv
                       + st[9]*Bv*Cv + st[10]*Bv*Dv + st[12]*Cv*Dv);
        double Q2 = 0.0;
#pragma unroll
        for (int i = 0; i < 4; i++)
#pragma unroll
            for (int j = 0; j < 6; j++) Q2 += u[i] * st[20 + i*6 + j] * g[j];
        double Q3 = 0.0;
        {
            int k = 0;
#pragma unroll
            for (int i = 0; i < 6; i++)
#pragma unroll
                for (int j = i; j < 6; j++) {
                    Q3 += (i == j ? 1.0 : 2.0) * g[i] * g[j] * st[44 + k];
                    k++;
                }
        }
        double S2 = Q1 - 2.0*Q2 + (double)MPTS * Q3;

        double N   = (double)NPIL * (double)MPTS;
        double mu  = S1 / N;
        double var = S2 / N - mu * mu;
        double s   = (double)gamma[c] / sqrt(var + 1e-3);
        double t   = (double)beta[c] - s * mu;

#pragma unroll
        for (int k = 0; k < 4; k++) s_u[c][k] = (float)(s * u[k]);
#pragma unroll
        for (int j = 0; j < 6; j++) s_g[c][j] = (float)(s * g[j]);
        s_t[c] = (float)t;
    }
    __syncthreads();

    if (c < 32) {
        int c0 = 2 * c, c1 = 2 * c + 1;
#pragma unroll
        for (int k = 0; k < 4; k++) d_UPK[c*4 + k] = pack2(s_u[c0][k], s_u[c1][k]);
#pragma unroll
        for (int j = 0; j < 6; j++) d_GPK[c*7 + j] = pack2(s_g[c0][j], s_g[c1][j]);
        d_GPK[c*7 + 6] = pack2(s_t[c0], s_t[c1]);
    }
}

// ---------------- vals: 8 threads/pillar x 8 channels (4 f32x2 pairs) ----------------
// thread g owns channel-pairs {2g, 2g+1, 16+2g, 16+2g+1}
//   -> channels {4g..4g+3} and {32+4g..32+4g+3}: both float4 stores coalesced.
__global__ void __launch_bounds__(256) vals_kernel(const float4* __restrict__ pil4) {
    __shared__ float4 spts[32][33];   // 32 pillars/block, pitch 33 float4

    int tid = threadIdx.x;
    int pg  = tid >> 3;              // pillar slot 0..31
    int g   = tid & 7;               // channel group
    int pbase = blockIdx.x * 32;
    int p = pbase + pg;

    // load 32 pillars (1024 float4) with 256 threads, coalesced
#pragma unroll
    for (int k = 0; k < 4; k++) {
        int idx = tid + k * 256;
        spts[idx >> 5][idx & 31] = pil4[(size_t)(pbase + (idx >> 5)) * MPTS + (idx & 31)];
    }

    int pr[4] = {2*g, 2*g + 1, 16 + 2*g, 16 + 2*g + 1};

    // per-thread weights: 4 channel-pairs + scalar BN consts
    unsigned long long ux[4], uy[4], uz[4], uw[4];
    float cst[8];
    {
        float4 w0 = d_wbuf4[p*2 + 0];
        float4 w1 = d_wbuf4[p*2 + 1];
        unsigned long long nm0 = splat2(-w0.x), nm1 = splat2(-w0.y), nm2 = splat2(-w0.z);
        unsigned long long nc0 = splat2(-w1.x), nc1 = splat2(-w1.y), nc2 = splat2(-w1.z);
#pragma unroll
        for (int k = 0; k < 4; k++) {
            int r = pr[k];
            ux[k] = d_UPK[r*4 + 0];
            uy[k] = d_UPK[r*4 + 1];
            uz[k] = d_UPK[r*4 + 2];
            uw[k] = d_UPK[r*4 + 3];
            unsigned long long a = d_GPK[r*7 + 6];      // t2
            FMA2(a, nm0, d_GPK[r*7 + 0]);
            FMA2(a, nm1, d_GPK[r*7 + 1]);
            FMA2(a, nm2, d_GPK[r*7 + 2]);
            FMA2(a, nc0, d_GPK[r*7 + 3]);
            FMA2(a, nc1, d_GPK[r*7 + 4]);
            FMA2(a, nc2, d_GPK[r*7 + 5]);
            UNPK2(cst[2*k], cst[2*k + 1], a);
        }
    }

    __syncthreads();

    float q[8];
#pragma unroll
    for (int k = 0; k < 8; k++) q[k] = -3.4e38f;

#pragma unroll
    for (int m = 0; m < MPTS; m++) {
        float4 v = spts[pg][m];
        unsigned long long vx = splat2(v.x);
        unsigned long long vy = splat2(v.y);
        unsigned long long vz = splat2(v.z);
        unsigned long long vw = splat2(v.w);
#pragma unroll
        for (int k = 0; k < 4; k++) {
            unsigned long long d;
            MUL2(d, vw, uw[k]);
            FMA2(d, vz, uz[k]);
            FMA2(d, vy, uy[k]);
            FMA2(d, vx, ux[k]);
            float lo, hi;
            UNPK2(lo, hi, d);
            q[2*k]     = fmaxf(q[2*k],     lo);
            q[2*k + 1] = fmaxf(q[2*k + 1], hi);
        }
    }

    // BN const + relu
    float4 r0, r1;
    r0.x = fmaxf(q[0] + cst[0], 0.f);
    r0.y = fmaxf(q[1] + cst[1], 0.f);
    r0.z = fmaxf(q[2] + cst[2], 0.f);
    r0.w = fmaxf(q[3] + cst[3], 0.f);
    r1.x = fmaxf(q[4] + cst[4], 0.f);
    r1.y = fmaxf(q[5] + cst[5], 0.f);
    r1.z = fmaxf(q[6] + cst[6], 0.f);
    r1.w = fmaxf(q[7] + cst[7], 0.f);

    // channels 4g..4g+3 at idx p*16+g ; channels 32+4g..32+4g+3 at p*16+8+g
    d_vals4[(size_t)p * 16 + g]     = r0;
    d_vals4[(size_t)p * 16 + 8 + g] = r1;
}

// ---------------- writer: pure streaming gather -> coalesced output ----------------
__global__ void __launch_bounds__(256) writer_kernel(float* __restrict__ out) {
    __shared__ int   s_slot[WCHUNK];    // -1 zero, 0..WMAX-1 slot, -2 direct-stored
    __shared__ int2  s_list[WCHUNK];    // (cell_local, pillar)
    __shared__ float s_vals[NCH * WPITCH];
    __shared__ int   s_n;

    int t    = threadIdx.x;
    int lane = t & 31;
    int warp = t >> 5;
    int b    = blockIdx.y;
    int c0   = blockIdx.x * WCHUNK;
    size_t rowbase = (size_t)b * NCH * NYNX + c0;

    if (t == 0) s_n = 0;
    __syncthreads();

    // --- phase 1: winners (coalesced) ---
    {
        int w = d_winner[b * NYNX + c0 + t];
        int slot = -1;
        if (w >= 0) {
            slot = atomicAdd(&s_n, 1);
            s_list[slot] = make_int2(t, w);
            if (slot >= WMAX) slot = -2;
        }
        s_slot[t] = slot;
    }
    __syncthreads();
    int n = s_n;

    // --- phase 2: gather vals rows (256B contiguous per winner, L2-resident) ---
    for (int idx = t; idx < n * 16; idx += 256) {
        int s = idx >> 4;
        int j = idx & 15;
        int2 e = s_list[s];
        float4 v = d_vals4[(size_t)e.y * 16 + j];
        // vals layout: idx j holds channels (j<8 ? 4j..4j+3 : 32+4(j-8)..)
        int cbase = (j < 8) ? (4*j) : (32 + 4*(j - 8));
        if (s < WMAX) {
            s_vals[(cbase + 0) * WPITCH + s] = v.x;
            s_vals[(cbase + 1) * WPITCH + s] = v.y;
            s_vals[(cbase + 2) * WPITCH + s] = v.z;
            s_vals[(cbase + 3) * WPITCH + s] = v.w;
        } else {
            // overflow (astronomically rare): direct scattered store
            out[rowbase + (size_t)(cbase + 0) * NYNX + e.x] = v.x;
            out[rowbase + (size_t)(cbase + 1) * NYNX + e.x] = v.y;
            out[rowbase + (size_t)(cbase + 2) * NYNX + e.x] = v.z;
            out[rowbase + (size_t)(cbase + 3) * NYNX + e.x] = v.w;
        }
    }
    __syncthreads();

    // --- phase 3: stream all 64 channel rows. warp w -> channels 8w..8w+7 ---
    int4 sl0 = ((const int4*)s_slot)[lane];        // cells 4*lane .. 4*lane+3
    int4 sl1 = ((const int4*)s_slot)[lane + 32];   // cells 128+4*lane ..
    int mn0 = min(min(sl0.x, sl0.y), min(sl0.z, sl0.w));
    int mn1 = min(min(sl1.x, sl1.y), min(sl1.z, sl1.w));
#pragma unroll
    for (int r = 0; r < 8; r++) {
        int ch = warp * 8 + r;
        const float* vrow = &s_vals[ch * WPITCH];
        float* dst = out + rowbase + (size_t)ch * NYNX;

        float4 v0;
        v0.x = (sl0.x >= 0) ? vrow[sl0.x] : 0.f;
        v0.y = (sl0.y >= 0) ? vrow[sl0.y] : 0.f;
        v0.z = (sl0.z >= 0) ? vrow[sl0.z] : 0.f;
        v0.w = (sl0.w >= 0) ? vrow[sl0.w] : 0.f;
        if (mn0 > -2) {
            __stcs((float4*)(dst + lane * 4), v0);
        } else {
            if (sl0.x != -2) dst[lane*4 + 0] = v0.x;
            if (sl0.y != -2) dst[lane*4 + 1] = v0.y;
            if (sl0.z != -2) dst[lane*4 + 2] = v0.z;
            if (sl0.w != -2) dst[lane*4 + 3] = v0.w;
        }

        float4 v1;
        v1.x = (sl1.x >= 0) ? vrow[sl1.x] : 0.f;
        v1.y = (sl1.y >= 0) ? vrow[sl1.y] : 0.f;
        v1.z = (sl1.z >= 0) ? vrow[sl1.z] : 0.f;
        v1.w = (sl1.w >= 0) ? vrow[sl1.w] : 0.f;
        if (mn1 > -2) {
            __stcs((float4*)(dst + 128 + lane * 4), v1);
        } else {
            if (sl1.x != -2) dst[128 + lane*4 + 0] = v1.x;
            if (sl1.y != -2) dst[128 + lane*4 + 1] = v1.y;
            if (sl1.z != -2) dst[128 + lane*4 + 2] = v1.z;
            if (sl1.w != -2) dst[128 + lane*4 + 3] = v1.w;
        }
    }
}

// ---------------- launch ----------------
extern "C" void kernel_launch(void* const* d_in, const int* in_sizes, int n_in,
                              void* d_out, int out_size) {
    const float4* pil4    = (const float4*)d_in[0];
    const int4*   coords4 = (const int4*)d_in[1];
    const int*    nump    = (const int*)d_in[2];
    const float*  W       = (const float*)d_in[3];
    const float*  gamma   = (const float*)d_in[4];
    const float*  beta    = (const float*)d_in[5];
    float* out = (float*)d_out;

    pre_init_kernel<<<592, 256>>>();
    stats_kernel<<<(NPIL + 255) / 256, 256>>>(pil4, coords4, nump);
    finalize_kernel<<<1, 64>>>(W, gamma, beta);
    vals_kernel<<<NPIL / 32, 256>>>(pil4);
    dim3 grid(NWCHUNK, BATCH);
    writer_kernel<<<grid, 256>>>(out);
}

// round 9
// speedup vs baseline: 3.0191x; 1.0720x over previous
#include <cuda_runtime.h>
#include <cstdint>

#define NPIL   96000
#define MPTS   32
#define BATCH  8
#define NXc    432
#define NYc    496
#define NYNX   (NYc*NXc)          /* 214272 */
#define NCH    64
#define WCHUNK 256
#define NWCHUNK (NYNX / WCHUNK)   /* 837 exactly */
#define WMAX   64
#define WPITCH 65

// ---------------- device scratch (static, no allocation) ----------------
__device__ double d_stats[65];
__device__ float4 d_wbuf4[NPIL * 2];          // per pillar: (mx,my,mz,0),(cx,cy,cz,0)
__device__ int    d_winner[BATCH * NYNX];     // 6.9 MB
__device__ float4 d_vals4[NPIL * 16];         // 24.6 MB: per pillar 64 UNSCALED channel maxes
__device__ unsigned long long d_UPK[32 * 4];  // channel-pair packed UNSCALED u (A,B,C,D)
__device__ unsigned long long d_GPK[32 * 7];  // channel-pair packed s*g0..g5, t
__device__ unsigned long long d_SPK[32];      // channel-pair packed s

// ---------------- f32x2 helpers ----------------
__device__ __forceinline__ unsigned long long splat2(float v) {
    unsigned long long r;
    asm("mov.b64 %0, {%1,%1};" : "=l"(r) : "f"(v));
    return r;
}
__device__ __forceinline__ unsigned long long pack2(float lo, float hi) {
    unsigned long long r;
    asm("mov.b64 %0, {%1,%2};" : "=l"(r) : "f"(lo), "f"(hi));
    return r;
}
#define FMA2(d, a, b)  asm("fma.rn.f32x2 %0, %1, %2, %0;" : "+l"(d) : "l"(a), "l"(b))
#define MUL2(d, a, b)  asm("mul.rn.f32x2 %0, %1, %2;"     : "=l"(d) : "l"(a), "l"(b))
#define UNPK2(lo, hi, d) asm("mov.b64 {%0,%1}, %2;" : "=f"(lo), "=f"(hi) : "l"(d))

// ---------------- pre-init: winner=-1, stats=0, pack unscaled U ----------------
__global__ void pre_init_kernel(const float* __restrict__ W) {
    int i = blockIdx.x * blockDim.x + threadIdx.x;
    int stride = gridDim.x * blockDim.x;
    const int nw = BATCH * NYNX;
    int4* w4 = (int4*)d_winner;
    int4 m1 = make_int4(-1, -1, -1, -1);
    for (int j = i; j < nw / 4; j += stride) w4[j] = m1;
    if (blockIdx.x == 0) {
        if (threadIdx.x < 65) d_stats[threadIdx.x] = 0.0;
        if (threadIdx.x >= 128 && threadIdx.x < 160) {
            int t = threadIdx.x - 128;
            int c0 = 2 * t, c1 = 2 * t + 1;
            float u0[4], u1[4];
            u0[0] = W[0*NCH+c0] + W[4*NCH+c0] + W[7*NCH+c0];
            u0[1] = W[1*NCH+c0] + W[5*NCH+c0] + W[8*NCH+c0];
            u0[2] = W[2*NCH+c0] + W[6*NCH+c0] + W[9*NCH+c0];
            u0[3] = W[3*NCH+c0];
            u1[0] = W[0*NCH+c1] + W[4*NCH+c1] + W[7*NCH+c1];
            u1[1] = W[1*NCH+c1] + W[5*NCH+c1] + W[8*NCH+c1];
            u1[2] = W[2*NCH+c1] + W[6*NCH+c1] + W[9*NCH+c1];
            u1[3] = W[3*NCH+c1];
#pragma unroll
            for (int k = 0; k < 4; k++) d_UPK[t*4 + k] = pack2(u0[k], u1[k]);
        }
    }
}

// ---------------- stats + winner + wbuf: one pass over pillar data ----------------
__global__ void __launch_bounds__(256) stats_kernel(const float4* __restrict__ pil4,
                             const int4*  __restrict__ coords4,
                             const int*   __restrict__ nump) {
    __shared__ float sred[8][65];
    int p = blockIdx.x * blockDim.x + threadIdx.x;
    int lane = threadIdx.x & 31;
    int warp = threadIdx.x >> 5;

    float acc[65];
#pragma unroll
    for (int i = 0; i < 65; i++) acc[i] = 0.f;

    if (p < NPIL) {
        float sx=0.f, sy=0.f, sz=0.f, sw=0.f;
        float xx=0.f,xy=0.f,xz=0.f,xw=0.f,yy=0.f,yz=0.f,yw=0.f,zz=0.f,zw=0.f,ww=0.f;
        const float4* vp = pil4 + (size_t)p * MPTS;
#pragma unroll 8
        for (int m = 0; m < MPTS; m++) {
            float4 v = vp[m];
            sx += v.x; sy += v.y; sz += v.z; sw += v.w;
            xx = fmaf(v.x, v.x, xx); xy = fmaf(v.x, v.y, xy);
            xz = fmaf(v.x, v.z, xz); xw = fmaf(v.x, v.w, xw);
            yy = fmaf(v.y, v.y, yy); yz = fmaf(v.y, v.z, yz);
            yw = fmaf(v.y, v.w, yw);
            zz = fmaf(v.z, v.z, zz); zw = fmaf(v.z, v.w, zw);
            ww = fmaf(v.w, v.w, ww);
        }
        int4 cd = coords4[p];                // (b, z, y, x)

        // winner scatter-order emulation (last index wins)
        int cell = cd.y + cd.z * NXc + cd.w;
        atomicMax(&d_winner[cd.x * NYNX + cell], p);

        float n = (float)nump[p];
        float mx = sx / n, my = sy / n, mz = sz / n;
        float ctrx = (float)cd.w * 0.16f + 0.08f;
        float ctry = (float)cd.z * 0.16f + (-39.6f);
        float ctrz = (float)cd.y * 4.0f  + (-1.0f);

        float sv[4] = {sx, sy, sz, sw};
        float w6[6] = {mx, my, mz, ctrx, ctry, ctrz};

        acc[0]=sx; acc[1]=sy; acc[2]=sz; acc[3]=sw;
        acc[4]=xx; acc[5]=xy; acc[6]=xz; acc[7]=xw; acc[8]=yy;
        acc[9]=yz; acc[10]=yw; acc[11]=zz; acc[12]=zw; acc[13]=ww;
#pragma unroll
        for (int j = 0; j < 6; j++) acc[14 + j] = w6[j];
#pragma unroll
        for (int i = 0; i < 4; i++)
#pragma unroll
            for (int j = 0; j < 6; j++) acc[20 + i*6 + j] = sv[i] * w6[j];
        {
            int k = 0;
#pragma unroll
            for (int i = 0; i < 6; i++)
#pragma unroll
                for (int j = i; j < 6; j++) { acc[44 + k] = w6[i] * w6[j]; k++; }
        }
        d_wbuf4[p*2 + 0] = make_float4(mx, my, mz, 0.f);
        d_wbuf4[p*2 + 1] = make_float4(ctrx, ctry, ctrz, 0.f);
    }

    // warp tree-reduce all 65 partials
#pragma unroll
    for (int i = 0; i < 65; i++) {
        float v = acc[i];
        v += __shfl_xor_sync(0xffffffffu, v, 16);
        v += __shfl_xor_sync(0xffffffffu, v, 8);
        v += __shfl_xor_sync(0xffffffffu, v, 4);
        v += __shfl_xor_sync(0xffffffffu, v, 2);
        v += __shfl_xor_sync(0xffffffffu, v, 1);
        acc[i] = v;
    }
    if (lane == 0) {
#pragma unroll
        for (int i = 0; i < 65; i++) sred[warp][i] = acc[i];
    }
    __syncthreads();

    if (threadIdx.x < 65) {
        float s = 0.f;
#pragma unroll
        for (int w = 0; w < 8; w++) s += sred[w][threadIdx.x];
        atomicAdd(&d_stats[threadIdx.x], (double)s);
    }
}

// ---------------- finalize: closed-form BN params, channel-pair packed ----------------
__global__ void finalize_kernel(const float* __restrict__ W,
                                const float* __restrict__ gamma,
                                const float* __restrict__ beta) {
    __shared__ float s_g[NCH][6];
    __shared__ float s_t[NCH];
    __shared__ float s_s[NCH];

    int c = threadIdx.x;
    if (c < NCH) {
        double A = (double)W[0*NCH+c] + (double)W[4*NCH+c] + (double)W[7*NCH+c];
        double Bv= (double)W[1*NCH+c] + (double)W[5*NCH+c] + (double)W[8*NCH+c];
        double Cv= (double)W[2*NCH+c] + (double)W[6*NCH+c] + (double)W[9*NCH+c];
        double Dv= (double)W[3*NCH+c];
        double u[4] = {A, Bv, Cv, Dv};
        double g[6];
#pragma unroll
        for (int j = 0; j < 6; j++) g[j] = (double)W[(4 + j)*NCH + c];

        double st[65];
#pragma unroll
        for (int i = 0; i < 65; i++) st[i] = d_stats[i];

        double S1 = u[0]*st[0] + u[1]*st[1] + u[2]*st[2] + u[3]*st[3];
        double sg = 0.0;
#pragma unroll
        for (int j = 0; j < 6; j++) sg += g[j] * st[14 + j];
        S1 -= (double)MPTS * sg;

        double Q1 = st[4]*A*A + st[8]*Bv*Bv + st[11]*Cv*Cv + st[13]*Dv*Dv
                  + 2.0*(st[5]*A*Bv + st[6]*A*Cv + st[7]*A*Dv
                       + st[9]*Bv*Cv + st[10]*Bv*Dv + st[12]*Cv*Dv);
        double Q2 = 0.0;
#pragma unroll
        for (int i = 0; i < 4; i++)
#pragma unroll
            for (int j = 0; j < 6; j++) Q2 += u[i] * st[20 + i*6 + j] * g[j];
        double Q3 = 0.0;
        {
            int k = 0;
#pragma unroll
            for (int i = 0; i < 6; i++)
#pragma unroll
                for (int j = i; j < 6; j++) {
                    Q3 += (i == j ? 1.0 : 2.0) * g[i] * g[j] * st[44 + k];
                    k++;
                }
        }
        double S2 = Q1 - 2.0*Q2 + (double)MPTS * Q3;

        double N   = (double)NPIL * (double)MPTS;
        double mu  = S1 / N;
        double var = S2 / N - mu * mu;
        double s   = (double)gamma[c] / sqrt(var + 1e-3);
        double t   = (double)beta[c] - s * mu;

#pragma unroll
        for (int j = 0; j < 6; j++) s_g[c][j] = (float)(s * g[j]);
        s_t[c] = (float)t;
        s_s[c] = (float)s;
    }
    __syncthreads();

    if (c < 32) {
        int c0 = 2 * c, c1 = 2 * c + 1;
#pragma unroll
        for (int j = 0; j < 6; j++) d_GPK[c*7 + j] = pack2(s_g[c0][j], s_g[c1][j]);
        d_GPK[c*7 + 6] = pack2(s_t[c0], s_t[c1]);
        d_SPK[c] = pack2(s_s[c0], s_s[c1]);
    }
}

// ---------------- vals: UNSCALED max_m(v.u) ; 8 threads/pillar x 8 channels ----------------
// thread g owns channel-pairs {2g, 2g+1, 16+2g, 16+2g+1}
//   -> channels {4g..4g+3} and {32+4g..32+4g+3}: both float4 stores coalesced.
__global__ void __launch_bounds__(256) vals_kernel(const float4* __restrict__ pil4) {
    __shared__ float4 spts[32][33];   // 32 pillars/block, pitch 33 float4

    int tid = threadIdx.x;
    int pg  = tid >> 3;              // pillar slot 0..31
    int g   = tid & 7;               // channel group
    int pbase = blockIdx.x * 32;
    int p = pbase + pg;

    // load 32 pillars (1024 float4) with 256 threads, coalesced
#pragma unroll
    for (int k = 0; k < 4; k++) {
        int idx = tid + k * 256;
        spts[idx >> 5][idx & 31] = pil4[(size_t)(pbase + (idx >> 5)) * MPTS + (idx & 31)];
    }

    int pr[4] = {2*g, 2*g + 1, 16 + 2*g, 16 + 2*g + 1};

    unsigned long long ux[4], uy[4], uz[4], uw[4];
#pragma unroll
    for (int k = 0; k < 4; k++) {
        int r = pr[k];
        ux[k] = d_UPK[r*4 + 0];
        uy[k] = d_UPK[r*4 + 1];
        uz[k] = d_UPK[r*4 + 2];
        uw[k] = d_UPK[r*4 + 3];
    }

    __syncthreads();

    float q[8];
#pragma unroll
    for (int k = 0; k < 8; k++) q[k] = -3.4e38f;

#pragma unroll
    for (int m = 0; m < MPTS; m++) {
        float4 v = spts[pg][m];
        unsigned long long vx = splat2(v.x);
        unsigned long long vy = splat2(v.y);
        unsigned long long vz = splat2(v.z);
        unsigned long long vw = splat2(v.w);
#pragma unroll
        for (int k = 0; k < 4; k++) {
            unsigned long long d;
            MUL2(d, vw, uw[k]);
            FMA2(d, vz, uz[k]);
            FMA2(d, vy, uy[k]);
            FMA2(d, vx, ux[k]);
            float lo, hi;
            UNPK2(lo, hi, d);
            q[2*k]     = fmaxf(q[2*k],     lo);
            q[2*k + 1] = fmaxf(q[2*k + 1], hi);
        }
    }

    // channels 4g..4g+3 at idx p*16+g ; channels 32+4g..32+4g+3 at p*16+8+g
    d_vals4[(size_t)p * 16 + g]     = make_float4(q[0], q[1], q[2], q[3]);
    d_vals4[(size_t)p * 16 + 8 + g] = make_float4(q[4], q[5], q[6], q[7]);
}

// ---------------- writer: affine+relu per winner, then coalesced stream ----------------
__global__ void __launch_bounds__(256) writer_kernel(float* __restrict__ out) {
    __shared__ int   s_slot[WCHUNK];    // -1 zero, 0..WMAX-1 slot, -2 direct-stored
    __shared__ int2  s_list[WCHUNK];    // (cell_local, pillar)
    __shared__ float s_vals[NCH * WPITCH];
    __shared__ int   s_n;

    int t    = threadIdx.x;
    int lane = t & 31;
    int warp = t >> 5;
    int b    = blockIdx.y;
    int c0   = blockIdx.x * WCHUNK;
    size_t rowbase = (size_t)b * NCH * NYNX + c0;

    if (t == 0) s_n = 0;
    __syncthreads();

    // --- phase 1: winners (coalesced) ---
    {
        int w = d_winner[b * NYNX + c0 + t];
        int slot = -1;
        if (w >= 0) {
            slot = atomicAdd(&s_n, 1);
            s_list[slot] = make_int2(t, w);
            if (slot >= WMAX) slot = -2;
        }
        s_slot[t] = slot;
    }
    __syncthreads();
    int n = s_n;

    // --- phase 2: gather M rows, apply BN affine + relu ---
    for (int idx = t; idx < n * 16; idx += 256) {
        int s = idx >> 4;
        int j = idx & 15;
        int2 e = s_list[s];
        int p = e.y;

        // channels covered by this float4
        int cbase = (j < 8) ? (4*j) : (32 + 4*(j - 8));
        int r0 = cbase >> 1;          // pair indices r0, r0+1

        // per-pillar w (L1 broadcast across the 16 threads of this winner)
        float4 w0 = d_wbuf4[p*2 + 0];
        float4 w1 = d_wbuf4[p*2 + 1];
        unsigned long long nm0 = splat2(-w0.x), nm1 = splat2(-w0.y), nm2 = splat2(-w0.z);
        unsigned long long nc0 = splat2(-w1.x), nc1 = splat2(-w1.y), nc2 = splat2(-w1.z);

        // M values (2 packed pairs)
        ulonglong2 M2 = ((const ulonglong2*)d_vals4)[(size_t)p * 16 + j];

        float v4[4];
#pragma unroll
        for (int k = 0; k < 2; k++) {
            int r = r0 + k;
            unsigned long long a = d_GPK[r*7 + 6];      // t2
            FMA2(a, nm0, d_GPK[r*7 + 0]);
            FMA2(a, nm1, d_GPK[r*7 + 1]);
            FMA2(a, nm2, d_GPK[r*7 + 2]);
            FMA2(a, nc0, d_GPK[r*7 + 3]);
            FMA2(a, nc1, d_GPK[r*7 + 4]);
            FMA2(a, nc2, d_GPK[r*7 + 5]);
            unsigned long long m = (k == 0) ? M2.x : M2.y;
            FMA2(a, m, d_SPK[r]);                       // s*M + cst
            float lo, hi;
            UNPK2(lo, hi, a);
            v4[2*k]     = fmaxf(lo, 0.f);
            v4[2*k + 1] = fmaxf(hi, 0.f);
        }

        if (s < WMAX) {
            s_vals[(cbase + 0) * WPITCH + s] = v4[0];
            s_vals[(cbase + 1) * WPITCH + s] = v4[1];
            s_vals[(cbase + 2) * WPITCH + s] = v4[2];
            s_vals[(cbase + 3) * WPITCH + s] = v4[3];
        } else {
            // overflow (astronomically rare): direct scattered store
            out[rowbase + (size_t)(cbase + 0) * NYNX + e.x] = v4[0];
            out[rowbase + (size_t)(cbase + 1) * NYNX + e.x] = v4[1];
            out[rowbase + (size_t)(cbase + 2) * NYNX + e.x] = v4[2];
            out[rowbase + (size_t)(cbase + 3) * NYNX + e.x] = v4[3];
        }
    }
    __syncthreads();

    // --- phase 3: stream all 64 channel rows. warp w -> channels 8w..8w+7 ---
    int4 sl0 = ((const int4*)s_slot)[lane];        // cells 4*lane .. 4*lane+3
    int4 sl1 = ((const int4*)s_slot)[lane + 32];   // cells 128+4*lane ..
    int mn0 = min(min(sl0.x, sl0.y), min(sl0.z, sl0.w));
    int mn1 = min(min(sl1.x, sl1.y), min(sl1.z, sl1.w));
#pragma unroll
    for (int r = 0; r < 8; r++) {
        int ch = warp * 8 + r;
        const float* vrow = &s_vals[ch * WPITCH];
        float* dst = out + rowbase + (size_t)ch * NYNX;

        float4 v0;
        v0.x = (sl0.x >= 0) ? vrow[sl0.x] : 0.f;
        v0.y = (sl0.y >= 0) ? vrow[sl0.y] : 0.f;
        v0.z = (sl0.z >= 0) ? vrow[sl0.z] : 0.f;
        v0.w = (sl0.w >= 0) ? vrow[sl0.w] : 0.f;
        if (mn0 > -2) {
            __stcs((float4*)(dst + lane * 4), v0);
        } else {
            if (sl0.x != -2) dst[lane*4 + 0] = v0.x;
            if (sl0.y != -2) dst[lane*4 + 1] = v0.y;
            if (sl0.z != -2) dst[lane*4 + 2] = v0.z;
            if (sl0.w != -2) dst[lane*4 + 3] = v0.w;
        }

        float4 v1;
        v1.x = (sl1.x >= 0) ? vrow[sl1.x] : 0.f;
        v1.y = (sl1.y >= 0) ? vrow[sl1.y] : 0.f;
        v1.z = (sl1.z >= 0) ? vrow[sl1.z] : 0.f;
        v1.w = (sl1.w >= 0) ? vrow[sl1.w] : 0.f;
        if (mn1 > -2) {
            __stcs((float4*)(dst + 128 + lane * 4), v1);
        } else {
            if (sl1.x != -2) dst[128 + lane*4 + 0] = v1.x;
            if (sl1.y != -2) dst[128 + lane*4 + 1] = v1.y;
            if (sl1.z != -2) dst[128 + lane*4 + 2] = v1.z;
            if (sl1.w != -2) dst[128 + lane*4 + 3] = v1.w;
        }
    }
}

// ---------------- launch: fork stats||vals via captured event edges ----------------
extern "C" void kernel_launch(void* const* d_in, const int* in_sizes, int n_in,
                              void* d_out, int out_size) {
    const float4* pil4    = (const float4*)d_in[0];
    const int4*   coords4 = (const int4*)d_in[1];
    const int*    nump    = (const int*)d_in[2];
    const float*  W       = (const float*)d_in[3];
    const float*  gamma   = (const float*)d_in[4];
    const float*  beta    = (const float*)d_in[5];
    float* out = (float*)d_out;

    static cudaStream_t s_side = nullptr;
    static cudaEvent_t  ev_fork = nullptr, ev_join = nullptr;
    if (s_side == nullptr) {
        cudaStreamCreateWithFlags(&s_side, cudaStreamNonBlocking);
        cudaEventCreateWithFlags(&ev_fork, cudaEventDisableTiming);
        cudaEventCreateWithFlags(&ev_join, cudaEventDisableTiming);
    }

    pre_init_kernel<<<592, 256>>>(W);

    // fork: side stream runs stats -> finalize, main stream runs vals
    cudaEventRecord(ev_fork, 0);
    cudaStreamWaitEvent(s_side, ev_fork, 0);

    stats_kernel<<<(NPIL + 255) / 256, 256, 0, s_side>>>(pil4, coords4, nump);
    finalize_kernel<<<1, 64, 0, s_side>>>(W, gamma, beta);
    cudaEventRecord(ev_join, s_side);

    vals_kernel<<<NPIL / 32, 256>>>(pil4);

    // join
    cudaStreamWaitEvent(0, ev_join, 0);
    dim3 grid(NWCHUNK, BATCH);
    writer_kernel<<<grid, 256>>>(out);
}